// round 3
// baseline (speedup 1.0000x reference)
#include <cuda_runtime.h>
#include <cuda_bf16.h>

// Problem constants (fixed shapes per reference)
#define BB   2
#define NN   2048
#define DD   1024
#define HH   16
#define DHH  64

typedef unsigned long long ull;

// Scratch: __device__ globals (allocation inside kernel_launch is forbidden)
__device__ float g_qp [BB * NN * DD];        // 16 MB : q @ Wq
__device__ float g_kvp[BB * NN * 2 * DD];    // 32 MB : kv @ Wkv  (cols [0:D)=K, [D:2D)=V)
__device__ float g_ao [BB * NN * DD];        // 16 MB : attention output (head-merged)

// ---------------- packed f32x2 helpers (FFMA2 path, rt=2 for 2 FMAs) ----------------
__device__ __forceinline__ ull pack2(float lo, float hi) {
    ull r; asm("mov.b64 %0, {%1,%2};" : "=l"(r) : "f"(lo), "f"(hi)); return r;
}
__device__ __forceinline__ ull dup2(float v) {
    ull r; asm("mov.b64 %0, {%1,%1};" : "=l"(r) : "f"(v)); return r;
}
__device__ __forceinline__ void fma2(ull &acc, ull a, ull b) {
    asm("fma.rn.f32x2 %0, %1, %2, %0;" : "+l"(acc) : "l"(a), "l"(b));
}
__device__ __forceinline__ void mul2ip(ull &x, ull a) {
    asm("mul.rn.f32x2 %0, %0, %1;" : "+l"(x) : "l"(a));
}
__device__ __forceinline__ float2 unpk(ull v) {
    float2 f; asm("mov.b64 {%0,%1}, %2;" : "=f"(f.x), "=f"(f.y) : "l"(v)); return f;
}

// =====================================================================================
// SGEMM: C[M,N] = A[M,K] @ B[K,N], all row-major fp32. M,N,K multiples of 128/8.
// 128x128 block tile, BK=8, 256 threads, 8x8 micro-tile, f32x2 accumulators
// (rows paired in the packed lanes).
// =====================================================================================
__global__ __launch_bounds__(256)
void sgemm128(const float* __restrict__ A, const float* __restrict__ B,
              float* __restrict__ C, int M, int N, int K)
{
    __shared__ float As[8][128];   // transposed: As[k][m]
    __shared__ float Bs[8][128];   // Bs[k][n]

    const int tid  = threadIdx.x;
    const int tx   = tid & 15;         // 0..15 (col groups)
    const int ty   = tid >> 4;         // 0..15 (row groups)
    const int rowA = tid >> 1;         // 0..127
    const int colA = (tid & 1) << 2;   // 0 or 4
    const int rowB = tid >> 5;         // 0..7
    const int colB = (tid & 31) << 2;  // 0..124

    const float* Ab = A + (size_t)(blockIdx.y * 128) * K;
    const float* Bb = B + (size_t)(blockIdx.x * 128);

    ull acc[4][8];
    #pragma unroll
    for (int i = 0; i < 4; i++)
        #pragma unroll
        for (int j = 0; j < 8; j++) acc[i][j] = 0ull;

    for (int kb = 0; kb < K; kb += 8) {
        float4 av = *(const float4*)(Ab + (size_t)rowA * K + kb + colA);
        float4 bv = *(const float4*)(Bb + (size_t)(kb + rowB) * N + colB);
        __syncthreads();   // previous tile's compute done before overwrite
        As[colA + 0][rowA] = av.x;
        As[colA + 1][rowA] = av.y;
        As[colA + 2][rowA] = av.z;
        As[colA + 3][rowA] = av.w;
        *(float4*)&Bs[rowB][colB] = bv;
        __syncthreads();

        #pragma unroll
        for (int k = 0; k < 8; k++) {
            float4 a0 = *(const float4*)&As[k][ty * 4];
            float4 a1 = *(const float4*)&As[k][64 + ty * 4];
            float4 b0 = *(const float4*)&Bs[k][tx * 4];
            float4 b1 = *(const float4*)&Bs[k][64 + tx * 4];
            ull ap[4] = { pack2(a0.x, a0.y), pack2(a0.z, a0.w),
                          pack2(a1.x, a1.y), pack2(a1.z, a1.w) };
            ull bd[8] = { dup2(b0.x), dup2(b0.y), dup2(b0.z), dup2(b0.w),
                          dup2(b1.x), dup2(b1.y), dup2(b1.z), dup2(b1.w) };
            #pragma unroll
            for (int i = 0; i < 4; i++)
                #pragma unroll
                for (int j = 0; j < 8; j++)
                    fma2(acc[i][j], ap[i], bd[j]);
        }
    }

    // Epilogue: acc[i][*] holds row-pairs. i=0,1 -> rows ty*4+{0,1},{2,3};
    // i=2,3 -> rows 64+ty*4+{0,1},{2,3}. Cols: j<4 -> tx*4+j, j>=4 -> 64+tx*4+(j-4).
    float* Cb = C + (size_t)(blockIdx.y * 128) * N + blockIdx.x * 128;
    #pragma unroll
    for (int i = 0; i < 4; i++) {
        int r0 = (i < 2) ? (ty * 4 + i * 2) : (64 + ty * 4 + (i - 2) * 2);
        float2 u[8];
        #pragma unroll
        for (int j = 0; j < 8; j++) u[j] = unpk(acc[i][j]);
        *(float4*)(Cb + (size_t)r0 * N + tx * 4)            = make_float4(u[0].x, u[1].x, u[2].x, u[3].x);
        *(float4*)(Cb + (size_t)r0 * N + 64 + tx * 4)       = make_float4(u[4].x, u[5].x, u[6].x, u[7].x);
        *(float4*)(Cb + (size_t)(r0 + 1) * N + tx * 4)      = make_float4(u[0].y, u[1].y, u[2].y, u[3].y);
        *(float4*)(Cb + (size_t)(r0 + 1) * N + 64 + tx * 4) = make_float4(u[4].y, u[5].y, u[6].y, u[7].y);
    }
}

// =====================================================================================
// Flash attention: grid (N/64, H, B), 256 threads.
// Block owns 64 Q rows of one head; loops over KV in 64-row tiles.
// S and PV both 4x4 micro-tiles with f32x2 (cols paired in packed lanes).
// Online softmax; 16-lane shfl row reductions (thread grid 16 ty x 16 tx).
// =====================================================================================
#define KSTR 64   // Ks row stride (d-major)
#define VSTR 68   // Vs row stride (padded: fixes 8-way STS conflict)

__global__ __launch_bounds__(256)
void attn_kernel(const float* __restrict__ qp, const float* __restrict__ kvp,
                 float* __restrict__ ao)
{
    extern __shared__ float sm[];
    float* Qs = sm;                      // [64][64]  r-major (scaled Q)
    float* Ks = sm + 4096;               // [64][KSTR] d-major: Ks[d*KSTR + c]
    float* Vs = sm + 4096 + 64 * KSTR;   // [64][VSTR] k-major: Vs[k*VSTR + d]
    float* Ps = Vs + 64 * VSTR;          // [64][64]  r-major

    const int tid = threadIdx.x;
    const int tx  = tid & 15;
    const int ty  = tid >> 4;
    const int b   = blockIdx.z;
    const int h   = blockIdx.y;
    const int q0  = blockIdx.x * 64;
    const int lr  = tid >> 2;            // 0..63 (load row)
    const int ld0 = (tid & 3) << 4;      // 0,16,32,48 (load col base)

    const float scale = 0.125f;          // Dh^-0.5

    // Load Q tile once, scale folded in
    const float* qb = qp + ((size_t)(b * NN + q0)) * DD + h * DHH;
    #pragma unroll
    for (int i = 0; i < 4; i++) {
        float4 v = *(const float4*)(qb + (size_t)lr * DD + ld0 + 4 * i);
        v.x *= scale; v.y *= scale; v.z *= scale; v.w *= scale;
        *(float4*)&Qs[lr * 64 + ld0 + 4 * i] = v;
    }

    float m[4], l[4];
    ull oacc[4][2];
    #pragma unroll
    for (int i = 0; i < 4; i++) { m[i] = -1e30f; l[i] = 0.f; oacc[i][0] = 0ull; oacc[i][1] = 0ull; }

    for (int t = 0; t < NN / 64; t++) {
        const int kv0 = t * 64;
        const float* kb = kvp + ((size_t)(b * NN + kv0)) * (2 * DD) + h * DHH;
        const float* vb = kb + DD;

        float4 kr[4], vr[4];
        #pragma unroll
        for (int i = 0; i < 4; i++) {
            kr[i] = *(const float4*)(kb + (size_t)lr * (2 * DD) + ld0 + 4 * i);
            vr[i] = *(const float4*)(vb + (size_t)lr * (2 * DD) + ld0 + 4 * i);
        }
        __syncthreads();   // previous PV reads of Ks/Vs/Ps done
        #pragma unroll
        for (int i = 0; i < 4; i++) {
            int d0 = ld0 + 4 * i;
            Ks[(d0 + 0) * KSTR + lr] = kr[i].x;   // transpose on store
            Ks[(d0 + 1) * KSTR + lr] = kr[i].y;
            Ks[(d0 + 2) * KSTR + lr] = kr[i].z;
            Ks[(d0 + 3) * KSTR + lr] = kr[i].w;
            *(float4*)&Vs[lr * VSTR + d0] = vr[i];
        }
        __syncthreads();

        // ---- S = Qs @ K^T (per-thread 4 rows x 4 cols, cols packed in pairs) ----
        ull sacc[4][2];
        #pragma unroll
        for (int i = 0; i < 4; i++) { sacc[i][0] = 0ull; sacc[i][1] = 0ull; }

        for (int d = 0; d < 64; d += 4) {
            float q4[4][4];
            #pragma unroll
            for (int i = 0; i < 4; i++) {
                float4 qv = *(const float4*)&Qs[(ty * 4 + i) * 64 + d];
                q4[i][0] = qv.x; q4[i][1] = qv.y; q4[i][2] = qv.z; q4[i][3] = qv.w;
            }
            #pragma unroll
            for (int dd = 0; dd < 4; dd++) {
                float4 kf = *(const float4*)&Ks[(d + dd) * KSTR + tx * 4];
                ull k01 = pack2(kf.x, kf.y), k23 = pack2(kf.z, kf.w);
                #pragma unroll
                for (int i = 0; i < 4; i++) {
                    ull qd = dup2(q4[i][dd]);
                    fma2(sacc[i][0], qd, k01);
                    fma2(sacc[i][1], qd, k23);
                }
            }
        }

        // ---- online softmax + write P ----
        #pragma unroll
        for (int i = 0; i < 4; i++) {
            float2 s01 = unpk(sacc[i][0]), s23 = unpk(sacc[i][1]);
            float mt = fmaxf(fmaxf(s01.x, s01.y), fmaxf(s23.x, s23.y));
            #pragma unroll
            for (int off = 8; off >= 1; off >>= 1)
                mt = fmaxf(mt, __shfl_xor_sync(0xffffffffu, mt, off));
            float mn = fmaxf(m[i], mt);
            float p0 = __expf(s01.x - mn), p1 = __expf(s01.y - mn);
            float p2 = __expf(s23.x - mn), p3 = __expf(s23.y - mn);
            float rs = (p0 + p1) + (p2 + p3);
            #pragma unroll
            for (int off = 8; off >= 1; off >>= 1)
                rs += __shfl_xor_sync(0xffffffffu, rs, off);
            float alpha = __expf(m[i] - mn);
            l[i] = l[i] * alpha + rs;
            m[i] = mn;
            ull ad = dup2(alpha);
            mul2ip(oacc[i][0], ad);
            mul2ip(oacc[i][1], ad);
            *(float4*)&Ps[(ty * 4 + i) * 64 + tx * 4] = make_float4(p0, p1, p2, p3);
        }
        __syncthreads();

        // ---- O += Ps @ Vs (same structure; d-cols packed in pairs) ----
        for (int k = 0; k < 64; k += 4) {
            float p4[4][4];
            #pragma unroll
            for (int i = 0; i < 4; i++) {
                float4 pv = *(const float4*)&Ps[(ty * 4 + i) * 64 + k];
                p4[i][0] = pv.x; p4[i][1] = pv.y; p4[i][2] = pv.z; p4[i][3] = pv.w;
            }
            #pragma unroll
            for (int kk = 0; kk < 4; kk++) {
                float4 vf = *(const float4*)&Vs[(k + kk) * VSTR + tx * 4];
                ull v01 = pack2(vf.x, vf.y), v23 = pack2(vf.z, vf.w);
                #pragma unroll
                for (int i = 0; i < 4; i++) {
                    ull pd = dup2(p4[i][kk]);
                    fma2(oacc[i][0], pd, v01);
                    fma2(oacc[i][1], pd, v23);
                }
            }
        }
    }

    // ---- epilogue: normalize and write head-merged layout [B,N,H*Dh] ----
    #pragma unroll
    for (int i = 0; i < 4; i++) {
        float inv = 1.0f / l[i];
        float2 o01 = unpk(oacc[i][0]), o23 = unpk(oacc[i][1]);
        float4 o = make_float4(o01.x * inv, o01.y * inv, o23.x * inv, o23.y * inv);
        *(float4*)(ao + ((size_t)(b * NN + q0 + ty * 4 + i)) * DD + h * DHH + tx * 4) = o;
    }
}

// =====================================================================================
// Launch: qp = q@Wq ; kvp = kv@Wkv ; flash-attn ; out = ao@Wout
// =====================================================================================
extern "C" void kernel_launch(void* const* d_in, const int* in_sizes, int n_in,
                              void* d_out, int out_size)
{
    const float* q    = (const float*)d_in[0];
    const float* kv   = (const float*)d_in[1];
    const float* Wq   = (const float*)d_in[2];
    const float* Wkv  = (const float*)d_in[3];
    const float* Wout = (const float*)d_in[4];
    float* out = (float*)d_out;

    float *qp, *kvp, *ao;
    cudaGetSymbolAddress((void**)&qp,  g_qp);
    cudaGetSymbolAddress((void**)&kvp, g_kvp);
    cudaGetSymbolAddress((void**)&ao,  g_ao);

    const int M = BB * NN;  // 4096
    dim3 blk(256);

    // 1) qp = q @ Wq          [4096,1024] = [4096,1024] @ [1024,1024]
    sgemm128<<<dim3(DD / 128, M / 128), blk>>>(q, Wq, qp, M, DD, DD);

    // 2) kvp = kv @ Wkv       [4096,2048] = [4096,1024] @ [1024,2048]
    sgemm128<<<dim3((2 * DD) / 128, M / 128), blk>>>(kv, Wkv, kvp, M, 2 * DD, DD);

    // 3) flash attention
    const int smem = (4096 + 64 * KSTR + 64 * VSTR + 4096) * (int)sizeof(float); // 66560 B
    cudaFuncSetAttribute(attn_kernel, cudaFuncAttributeMaxDynamicSharedMemorySize, smem);
    attn_kernel<<<dim3(NN / 64, HH, BB), blk, smem>>>(qp, kvp, ao);

    // 4) out = ao @ Wout      [4096,1024] = [4096,1024] @ [1024,1024]
    sgemm128<<<dim3(DD / 128, M / 128), blk>>>(ao, Wout, out, M, DD, DD);
}

// round 5
// speedup vs baseline: 1.3667x; 1.3667x over previous
#include <cuda_runtime.h>
#include <cuda_bf16.h>
#include <cstdint>

// Problem constants (fixed shapes per reference)
#define BB   2
#define NN   2048
#define DD   1024
#define HH   16
#define DHH  64

typedef unsigned long long ull;

// ---------------- scratch (__device__ globals; allocation is forbidden) ----------------
__device__ __align__(16) float g_qp [BB * NN * DD];        // 16 MB : q @ Wq
__device__ __align__(16) float g_kvp[BB * NN * 2 * DD];    // 32 MB : kv @ Wkv
__device__ __align__(16) float g_ao [BB * NN * DD];        // 16 MB : attention output
__device__ __align__(16) __nv_bfloat16 g_ahi[BB * NN * DD];      // activation split hi
__device__ __align__(16) __nv_bfloat16 g_alo[BB * NN * DD];      // activation split lo
__device__ __align__(16) __nv_bfloat16 g_wthi[2 * DD * DD];      // weight^T split hi [N,K]
__device__ __align__(16) __nv_bfloat16 g_wtlo[2 * DD * DD];      // weight^T split lo [N,K]

// ---------------- helpers ----------------
__device__ __forceinline__ uint32_t smem_to_u32(const void* p) {
    uint32_t a;
    asm("{ .reg .u64 t; cvta.to.shared.u64 t, %1; cvt.u32.u64 %0, t; }" : "=r"(a) : "l"(p));
    return a;
}
#define SMEM_SWIZZLE_128B(off) ((off) ^ (((off) >> 3) & 0x70))

__device__ __forceinline__ void cp_async16(uint32_t s, const void* g) {
    asm volatile("cp.async.cg.shared.global [%0], [%1], 16;" :: "r"(s), "l"(g));
}
#define CP_COMMIT() asm volatile("cp.async.commit_group;" ::: "memory")
#define CP_WAIT0()  asm volatile("cp.async.wait_group 0;" ::: "memory")

#define LDSM_X4(r0, r1, r2, r3, addr) \
    asm volatile("ldmatrix.sync.aligned.m8n8.x4.shared.b16 {%0,%1,%2,%3}, [%4];" \
                 : "=r"(r0), "=r"(r1), "=r"(r2), "=r"(r3) : "r"(addr))

__device__ __forceinline__ void mma16816(float* d, const uint32_t* a, const uint32_t* b) {
    asm volatile("mma.sync.aligned.m16n8k16.row.col.f32.bf16.bf16.f32 "
        "{%0,%1,%2,%3},{%4,%5,%6,%7},{%8,%9},{%0,%1,%2,%3};"
        : "+f"(d[0]), "+f"(d[1]), "+f"(d[2]), "+f"(d[3])
        : "r"(a[0]), "r"(a[1]), "r"(a[2]), "r"(a[3]), "r"(b[0]), "r"(b[1]));
}

// =====================================================================================
// Prep kernels: fp32 -> (bf16 hi, bf16 lo) split; weight transpose+split.
// =====================================================================================
__global__ __launch_bounds__(256)
void split_act(const float* __restrict__ x, __nv_bfloat16* __restrict__ hi,
               __nv_bfloat16* __restrict__ lo, int n)
{
    int i = (blockIdx.x * 256 + threadIdx.x) * 4;
    if (i >= n) return;
    float4 v = *(const float4*)(x + i);
    float vv[4] = { v.x, v.y, v.z, v.w };
    __nv_bfloat16 hv[4], lv[4];
    #pragma unroll
    for (int j = 0; j < 4; j++) {
        hv[j] = __float2bfloat16(vv[j]);
        lv[j] = __float2bfloat16(vv[j] - __bfloat162float(hv[j]));
    }
    *(__nv_bfloat162*)(hi + i)     = __nv_bfloat162(hv[0], hv[1]);
    *(__nv_bfloat162*)(hi + i + 2) = __nv_bfloat162(hv[2], hv[3]);
    *(__nv_bfloat162*)(lo + i)     = __nv_bfloat162(lv[0], lv[1]);
    *(__nv_bfloat162*)(lo + i + 2) = __nv_bfloat162(lv[2], lv[3]);
}

// W[K,N] row-major  ->  Wt_hi/lo[N,K] (K-major, as the mma.sync col-major B wants)
__global__ __launch_bounds__(256)
void transpose_split(const float* __restrict__ W, __nv_bfloat16* __restrict__ Thi,
                     __nv_bfloat16* __restrict__ Tlo, int Kd, int Nd)
{
    __shared__ float t[32][33];
    int nb = blockIdx.x * 32, kb = blockIdx.y * 32;
    int tx = threadIdx.x, ty = threadIdx.y;          // (32, 8)
    #pragma unroll
    for (int i = 0; i < 32; i += 8)
        t[ty + i][tx] = W[(size_t)(kb + ty + i) * Nd + nb + tx];
    __syncthreads();
    #pragma unroll
    for (int i = 0; i < 32; i += 8) {
        float v = t[tx][ty + i];                     // = W[kb+tx][nb+ty+i]
        __nv_bfloat16 h = __float2bfloat16(v);
        float r = v - __bfloat162float(h);
        size_t o = (size_t)(nb + ty + i) * Kd + kb + tx;
        Thi[o] = h;
        Tlo[o] = __float2bfloat16(r);
    }
}

// =====================================================================================
// mma.sync split-bf16 GEMM: C[M,N] = A[M,K] @ W, with B = W^T given as [N,K] K-major.
// CTA tile 128x128, BK=64 (128B rows, SW128), cp.async double buffer (2 x 64KB).
// 8 warps: 2(m) x 4(n), warp tile 64x32 -> 4 m16 x 4 n8 fragments.
// 3 HMMA products per fragment per K16 step (hi*hi + hi*lo + lo*hi).
// =====================================================================================
#define GEMM_SMEM (2 * 65536)

__global__ __launch_bounds__(256)
void gemm_tc(const __nv_bfloat16* __restrict__ Ahi, const __nv_bfloat16* __restrict__ Alo,
             const __nv_bfloat16* __restrict__ Bhi, const __nv_bfloat16* __restrict__ Blo,
             float* __restrict__ C, int M, int N, int K)
{
    extern __shared__ char smem[];
    const uint32_t smem_base = smem_to_u32(smem);
    const int tid = threadIdx.x;
    const int wid = tid >> 5;
    const int lid = tid & 31;
    const int m0 = blockIdx.y * 128;
    const int n0 = blockIdx.x * 128;
    const int warp_m = (wid & 1) * 64;
    const int warp_n = (wid >> 1) * 32;

    // per-thread staging geometry (fixed across chunks): 4 tiles x 4 iters of 16B
    // tile t: 0=Ahi 1=Alo 2=Bhi 3=Blo ; each tile = 128 rows x 128B, SW128
    const int s_row = (tid >> 3) & 127;        // with it*256 added below
    const int s_seg = tid & 7;

    float d[4][4][4];
    #pragma unroll
    for (int mi = 0; mi < 4; mi++)
        #pragma unroll
        for (int ni = 0; ni < 4; ni++)
            #pragma unroll
            for (int j = 0; j < 4; j++) d[mi][ni][j] = 0.f;

    const int NCH = K >> 6;

    // ---- stage chunk 0 ----
    #pragma unroll
    for (int t = 0; t < 4; t++) {
        const __nv_bfloat16* src = (t == 0) ? Ahi : (t == 1) ? Alo : (t == 2) ? Bhi : Blo;
        const int base_row = (t < 2) ? m0 : n0;
        #pragma unroll
        for (int it = 0; it < 4; it++) {
            int idx = tid + it * 256;
            int row = idx >> 3, seg = idx & 7;
            cp_async16(smem_base + t * 16384 + SMEM_SWIZZLE_128B((uint32_t)(row * 128 + seg * 16)),
                       src + (size_t)(base_row + row) * K + seg * 8);
        }
    }
    CP_COMMIT();
    CP_WAIT0();
    __syncthreads();

    for (int c = 0; c < NCH; c++) {
        const uint32_t sb = smem_base + (c & 1) * 65536;

        // prefetch next chunk into the other buffer
        if (c + 1 < NCH) {
            const uint32_t nb = smem_base + ((c + 1) & 1) * 65536;
            const int kc = (c + 1) << 6;
            #pragma unroll
            for (int t = 0; t < 4; t++) {
                const __nv_bfloat16* src = (t == 0) ? Ahi : (t == 1) ? Alo : (t == 2) ? Bhi : Blo;
                const int base_row = (t < 2) ? m0 : n0;
                #pragma unroll
                for (int it = 0; it < 4; it++) {
                    int idx = tid + it * 256;
                    int row = idx >> 3, seg = idx & 7;
                    cp_async16(nb + t * 16384 + SMEM_SWIZZLE_128B((uint32_t)(row * 128 + seg * 16)),
                               src + (size_t)(base_row + row) * K + kc + seg * 8);
                }
            }
            CP_COMMIT();
        }

        // ---- compute current chunk: 4 K16 steps ----
        #pragma unroll
        for (int ks = 0; ks < 4; ks++) {
            uint32_t ah[4][4], al[4][4];
            #pragma unroll
            for (int mi = 0; mi < 4; mi++) {
                uint32_t off = SMEM_SWIZZLE_128B(
                    (uint32_t)((warp_m + mi * 16 + (lid & 15)) * 128 + ks * 32 + ((lid >> 4) & 1) * 16));
                LDSM_X4(ah[mi][0], ah[mi][1], ah[mi][2], ah[mi][3], sb + off);
                LDSM_X4(al[mi][0], al[mi][1], al[mi][2], al[mi][3], sb + 16384 + off);
            }
            uint32_t bh[4][2], bl[4][2];
            #pragma unroll
            for (int pr = 0; pr < 2; pr++) {
                uint32_t off = SMEM_SWIZZLE_128B(
                    (uint32_t)((warp_n + pr * 16 + ((lid >> 4) & 1) * 8 + (lid & 7)) * 128
                               + ks * 32 + ((lid >> 3) & 1) * 16));
                LDSM_X4(bh[pr * 2][0], bh[pr * 2][1], bh[pr * 2 + 1][0], bh[pr * 2 + 1][1],
                        sb + 32768 + off);
                LDSM_X4(bl[pr * 2][0], bl[pr * 2][1], bl[pr * 2 + 1][0], bl[pr * 2 + 1][1],
                        sb + 49152 + off);
            }
            // hi*hi, then hi*lo, then lo*hi — dependent MMAs 16 apart
            #pragma unroll
            for (int mi = 0; mi < 4; mi++)
                #pragma unroll
                for (int ni = 0; ni < 4; ni++)
                    mma16816(d[mi][ni], ah[mi], bh[ni]);
            #pragma unroll
            for (int mi = 0; mi < 4; mi++)
                #pragma unroll
                for (int ni = 0; ni < 4; ni++)
                    mma16816(d[mi][ni], ah[mi], bl[ni]);
            #pragma unroll
            for (int mi = 0; mi < 4; mi++)
                #pragma unroll
                for (int ni = 0; ni < 4; ni++)
                    mma16816(d[mi][ni], al[mi], bh[ni]);
        }

        if (c + 1 < NCH) {
            CP_WAIT0();
            __syncthreads();
        }
    }

    // ---- epilogue: d frag -> C (float2 per fragment-half) ----
    #pragma unroll
    for (int mi = 0; mi < 4; mi++) {
        const int row = m0 + warp_m + mi * 16 + (lid >> 2);
        #pragma unroll
        for (int ni = 0; ni < 4; ni++) {
            const int col = n0 + warp_n + ni * 8 + (lid & 3) * 2;
            *(float2*)(C + (size_t)row * N + col)       = make_float2(d[mi][ni][0], d[mi][ni][1]);
            *(float2*)(C + (size_t)(row + 8) * N + col) = make_float2(d[mi][ni][2], d[mi][ni][3]);
        }
    }
    (void)s_row; (void)s_seg;
}

// =====================================================================================
// Flash attention (unchanged from R2 passing kernel): packed-f32x2 SIMT.
// =====================================================================================
__device__ __forceinline__ ull pack2(float lo, float hi) {
    ull r; asm("mov.b64 %0, {%1,%2};" : "=l"(r) : "f"(lo), "f"(hi)); return r;
}
__device__ __forceinline__ ull dup2(float v) {
    ull r; asm("mov.b64 %0, {%1,%1};" : "=l"(r) : "f"(v)); return r;
}
__device__ __forceinline__ void fma2(ull &acc, ull a, ull b) {
    asm("fma.rn.f32x2 %0, %1, %2, %0;" : "+l"(acc) : "l"(a), "l"(b));
}
__device__ __forceinline__ void mul2ip(ull &x, ull a) {
    asm("mul.rn.f32x2 %0, %0, %1;" : "+l"(x) : "l"(a));
}
__device__ __forceinline__ float2 unpk(ull v) {
    float2 f; asm("mov.b64 {%0,%1}, %2;" : "=f"(f.x), "=f"(f.y) : "l"(v)); return f;
}

#define KSTR 64
#define VSTR 68

__global__ __launch_bounds__(256)
void attn_kernel(const float* __restrict__ qp, const float* __restrict__ kvp,
                 float* __restrict__ ao)
{
    extern __shared__ float sm[];
    float* Qs = sm;
    float* Ks = sm + 4096;
    float* Vs = sm + 4096 + 64 * KSTR;
    float* Ps = Vs + 64 * VSTR;

    const int tid = threadIdx.x;
    const int tx  = tid & 15;
    const int ty  = tid >> 4;
    const int b   = blockIdx.z;
    const int h   = blockIdx.y;
    const int q0  = blockIdx.x * 64;
    const int lr  = tid >> 2;
    const int ld0 = (tid & 3) << 4;

    const float scale = 0.125f;

    const float* qb = qp + ((size_t)(b * NN + q0)) * DD + h * DHH;
    #pragma unroll
    for (int i = 0; i < 4; i++) {
        float4 v = *(const float4*)(qb + (size_t)lr * DD + ld0 + 4 * i);
        v.x *= scale; v.y *= scale; v.z *= scale; v.w *= scale;
        *(float4*)&Qs[lr * 64 + ld0 + 4 * i] = v;
    }

    float m[4], l[4];
    ull oacc[4][2];
    #pragma unroll
    for (int i = 0; i < 4; i++) { m[i] = -1e30f; l[i] = 0.f; oacc[i][0] = 0ull; oacc[i][1] = 0ull; }

    for (int t = 0; t < NN / 64; t++) {
        const int kv0 = t * 64;
        const float* kb = kvp + ((size_t)(b * NN + kv0)) * (2 * DD) + h * DHH;
        const float* vb = kb + DD;

        float4 kr[4], vr[4];
        #pragma unroll
        for (int i = 0; i < 4; i++) {
            kr[i] = *(const float4*)(kb + (size_t)lr * (2 * DD) + ld0 + 4 * i);
            vr[i] = *(const float4*)(vb + (size_t)lr * (2 * DD) + ld0 + 4 * i);
        }
        __syncthreads();
        #pragma unroll
        for (int i = 0; i < 4; i++) {
            int d0 = ld0 + 4 * i;
            Ks[(d0 + 0) * KSTR + lr] = kr[i].x;
            Ks[(d0 + 1) * KSTR + lr] = kr[i].y;
            Ks[(d0 + 2) * KSTR + lr] = kr[i].z;
            Ks[(d0 + 3) * KSTR + lr] = kr[i].w;
            *(float4*)&Vs[lr * VSTR + d0] = vr[i];
        }
        __syncthreads();

        ull sacc[4][2];
        #pragma unroll
        for (int i = 0; i < 4; i++) { sacc[i][0] = 0ull; sacc[i][1] = 0ull; }

        for (int d = 0; d < 64; d += 4) {
            float q4[4][4];
            #pragma unroll
            for (int i = 0; i < 4; i++) {
                float4 qv = *(const float4*)&Qs[(ty * 4 + i) * 64 + d];
                q4[i][0] = qv.x; q4[i][1] = qv.y; q4[i][2] = qv.z; q4[i][3] = qv.w;
            }
            #pragma unroll
            for (int dd = 0; dd < 4; dd++) {
                float4 kf = *(const float4*)&Ks[(d + dd) * KSTR + tx * 4];
                ull k01 = pack2(kf.x, kf.y), k23 = pack2(kf.z, kf.w);
                #pragma unroll
                for (int i = 0; i < 4; i++) {
                    ull qd = dup2(q4[i][dd]);
                    fma2(sacc[i][0], qd, k01);
                    fma2(sacc[i][1], qd, k23);
                }
            }
        }

        #pragma unroll
        for (int i = 0; i < 4; i++) {
            float2 s01 = unpk(sacc[i][0]), s23 = unpk(sacc[i][1]);
            float mt = fmaxf(fmaxf(s01.x, s01.y), fmaxf(s23.x, s23.y));
            #pragma unroll
            for (int off = 8; off >= 1; off >>= 1)
                mt = fmaxf(mt, __shfl_xor_sync(0xffffffffu, mt, off));
            float mn = fmaxf(m[i], mt);
            float p0 = __expf(s01.x - mn), p1 = __expf(s01.y - mn);
            float p2 = __expf(s23.x - mn), p3 = __expf(s23.y - mn);
            float rs = (p0 + p1) + (p2 + p3);
            #pragma unroll
            for (int off = 8; off >= 1; off >>= 1)
                rs += __shfl_xor_sync(0xffffffffu, rs, off);
            float alpha = __expf(m[i] - mn);
            l[i] = l[i] * alpha + rs;
            m[i] = mn;
            ull ad = dup2(alpha);
            mul2ip(oacc[i][0], ad);
            mul2ip(oacc[i][1], ad);
            *(float4*)&Ps[(ty * 4 + i) * 64 + tx * 4] = make_float4(p0, p1, p2, p3);
        }
        __syncthreads();

        for (int k = 0; k < 64; k += 4) {
            float p4[4][4];
            #pragma unroll
            for (int i = 0; i < 4; i++) {
                float4 pv = *(const float4*)&Ps[(ty * 4 + i) * 64 + k];
                p4[i][0] = pv.x; p4[i][1] = pv.y; p4[i][2] = pv.z; p4[i][3] = pv.w;
            }
            #pragma unroll
            for (int kk = 0; kk < 4; kk++) {
                float4 vf = *(const float4*)&Vs[(k + kk) * VSTR + tx * 4];
                ull v01 = pack2(vf.x, vf.y), v23 = pack2(vf.z, vf.w);
                #pragma unroll
                for (int i = 0; i < 4; i++) {
                    ull pd = dup2(p4[i][kk]);
                    fma2(oacc[i][0], pd, v01);
                    fma2(oacc[i][1], pd, v23);
                }
            }
        }
    }

    #pragma unroll
    for (int i = 0; i < 4; i++) {
        float inv = 1.0f / l[i];
        float2 o01 = unpk(oacc[i][0]), o23 = unpk(oacc[i][1]);
        float4 o = make_float4(o01.x * inv, o01.y * inv, o23.x * inv, o23.y * inv);
        *(float4*)(ao + ((size_t)(b * NN + q0 + ty * 4 + i)) * DD + h * DHH + tx * 4) = o;
    }
}

// =====================================================================================
// Launch
// =====================================================================================
extern "C" void kernel_launch(void* const* d_in, const int* in_sizes, int n_in,
                              void* d_out, int out_size)
{
    const float* q    = (const float*)d_in[0];
    const float* kv   = (const float*)d_in[1];
    const float* Wq   = (const float*)d_in[2];
    const float* Wkv  = (const float*)d_in[3];
    const float* Wout = (const float*)d_in[4];
    float* out = (float*)d_out;

    float *qp, *kvp, *ao;
    __nv_bfloat16 *ahi, *alo, *wthi, *wtlo;
    cudaGetSymbolAddress((void**)&qp,   g_qp);
    cudaGetSymbolAddress((void**)&kvp,  g_kvp);
    cudaGetSymbolAddress((void**)&ao,   g_ao);
    cudaGetSymbolAddress((void**)&ahi,  g_ahi);
    cudaGetSymbolAddress((void**)&alo,  g_alo);
    cudaGetSymbolAddress((void**)&wthi, g_wthi);
    cudaGetSymbolAddress((void**)&wtlo, g_wtlo);

    const int M = BB * NN;              // 4096
    const int nact = M * DD;            // 4M elements

    cudaFuncSetAttribute(gemm_tc, cudaFuncAttributeMaxDynamicSharedMemorySize, GEMM_SMEM);

    dim3 tb(256);
    dim3 tt(32, 8);

    // ---- 1) qp = q @ Wq ----
    split_act<<<nact / 4 / 256, tb>>>(q, ahi, alo, nact);
    transpose_split<<<dim3(DD / 32, DD / 32), tt>>>(Wq, wthi, wtlo, DD, DD);
    gemm_tc<<<dim3(DD / 128, M / 128), tb, GEMM_SMEM>>>(ahi, alo, wthi, wtlo, qp, M, DD, DD);

    // ---- 2) kvp = kv @ Wkv ----
    split_act<<<nact / 4 / 256, tb>>>(kv, ahi, alo, nact);
    transpose_split<<<dim3((2 * DD) / 32, DD / 32), tt>>>(Wkv, wthi, wtlo, DD, 2 * DD);
    gemm_tc<<<dim3((2 * DD) / 128, M / 128), tb, GEMM_SMEM>>>(ahi, alo, wthi, wtlo, kvp, M, 2 * DD, DD);

    // ---- 3) flash attention ----
    const int smem = (4096 + 64 * KSTR + 64 * VSTR + 4096) * (int)sizeof(float); // 66560 B
    cudaFuncSetAttribute(attn_kernel, cudaFuncAttributeMaxDynamicSharedMemorySize, smem);
    attn_kernel<<<dim3(NN / 64, HH, BB), tb, smem>>>(qp, kvp, ao);

    // ---- 4) out = ao @ Wout ----
    split_act<<<nact / 4 / 256, tb>>>(ao, ahi, alo, nact);
    transpose_split<<<dim3(DD / 32, DD / 32), tt>>>(Wout, wthi, wtlo, DD, DD);
    gemm_tc<<<dim3(DD / 128, M / 128), tb, GEMM_SMEM>>>(ahi, alo, wthi, wtlo, out, M, DD, DD);
}

// round 7
// speedup vs baseline: 2.9102x; 2.1293x over previous
#include <cuda_runtime.h>
#include <cuda_bf16.h>
#include <cstdint>

// Problem constants (fixed shapes per reference)
#define BB   2
#define NN   2048
#define DD   1024
#define HH   16
#define DHH  64
#define NT   (NN / 64)   // 32 KV tiles of 64

// ---------------- scratch (__device__ globals; allocation is forbidden) ----------------
__device__ __align__(16) __nv_bfloat16 g_ahi [BB * NN * DD];     // act split hi (also ao hi)
__device__ __align__(16) __nv_bfloat16 g_alo [BB * NN * DD];     // act split lo (also ao lo)
__device__ __align__(16) __nv_bfloat16 g_qphi[BB * NN * DD];     // qp split hi (0.125 folded)
__device__ __align__(16) __nv_bfloat16 g_qplo[BB * NN * DD];
__device__ __align__(16) __nv_bfloat16 g_kvphi[BB * NN * 2 * DD];
__device__ __align__(16) __nv_bfloat16 g_kvplo[BB * NN * 2 * DD];
__device__ __align__(16) __nv_bfloat16 g_wthi[2 * DD * DD];      // weight^T split hi [N,K]
__device__ __align__(16) __nv_bfloat16 g_wtlo[2 * DD * DD];

// ---------------- helpers ----------------
__device__ __forceinline__ uint32_t smem_to_u32(const void* p) {
    uint32_t a;
    asm("{ .reg .u64 t; cvta.to.shared.u64 t, %1; cvt.u32.u64 %0, t; }" : "=r"(a) : "l"(p));
    return a;
}
#define SMEM_SWIZZLE_128B(off) ((off) ^ (((off) >> 3) & 0x70))

__device__ __forceinline__ void cp_async16(uint32_t s, const void* g) {
    asm volatile("cp.async.cg.shared.global [%0], [%1], 16;" :: "r"(s), "l"(g));
}
#define CP_COMMIT() asm volatile("cp.async.commit_group;" ::: "memory")
#define CP_WAIT0()  asm volatile("cp.async.wait_group 0;" ::: "memory")
#define CP_WAIT1()  asm volatile("cp.async.wait_group 1;" ::: "memory")

#define LDSM_X4(r0, r1, r2, r3, addr) \
    asm volatile("ldmatrix.sync.aligned.m8n8.x4.shared.b16 {%0,%1,%2,%3}, [%4];" \
                 : "=r"(r0), "=r"(r1), "=r"(r2), "=r"(r3) : "r"(addr))
#define LDSM_X4_T(r0, r1, r2, r3, addr) \
    asm volatile("ldmatrix.sync.aligned.m8n8.x4.trans.shared.b16 {%0,%1,%2,%3}, [%4];" \
                 : "=r"(r0), "=r"(r1), "=r"(r2), "=r"(r3) : "r"(addr))

__device__ __forceinline__ void mma16816(float* d, const uint32_t* a, const uint32_t* b) {
    asm volatile("mma.sync.aligned.m16n8k16.row.col.f32.bf16.bf16.f32 "
        "{%0,%1,%2,%3},{%4,%5,%6,%7},{%8,%9},{%0,%1,%2,%3};"
        : "+f"(d[0]), "+f"(d[1]), "+f"(d[2]), "+f"(d[3])
        : "r"(a[0]), "r"(a[1]), "r"(a[2]), "r"(a[3]), "r"(b[0]), "r"(b[1]));
}

// pack two fp32 -> bf16x2 (lo element in low 16 bits)
__device__ __forceinline__ uint32_t pkbf(float lo, float hi) {
    uint32_t r; asm("cvt.rn.bf16x2.f32 %0, %1, %2;" : "=r"(r) : "f"(hi), "f"(lo)); return r;
}
__device__ __forceinline__ float lo2f(uint32_t u) { return __uint_as_float(u << 16); }
__device__ __forceinline__ float hi2f(uint32_t u) { return __uint_as_float(u & 0xffff0000u); }

// =====================================================================================
// Prep kernels
// =====================================================================================
__global__ __launch_bounds__(256)
void split_act(const float* __restrict__ x, __nv_bfloat16* __restrict__ hi,
               __nv_bfloat16* __restrict__ lo, int n)
{
    int i = (blockIdx.x * 256 + threadIdx.x) * 4;
    if (i >= n) return;
    float4 v = *(const float4*)(x + i);
    float vv[4] = { v.x, v.y, v.z, v.w };
    uint32_t h01 = pkbf(vv[0], vv[1]), h23 = pkbf(vv[2], vv[3]);
    uint32_t l01 = pkbf(vv[0] - lo2f(h01), vv[1] - hi2f(h01));
    uint32_t l23 = pkbf(vv[2] - lo2f(h23), vv[3] - hi2f(h23));
    *(uint32_t*)(hi + i)     = h01;
    *(uint32_t*)(hi + i + 2) = h23;
    *(uint32_t*)(lo + i)     = l01;
    *(uint32_t*)(lo + i + 2) = l23;
}

// W[K,N] row-major  ->  Wt_hi/lo[N,K] (K-major)
__global__ __launch_bounds__(256)
void transpose_split(const float* __restrict__ W, __nv_bfloat16* __restrict__ Thi,
                     __nv_bfloat16* __restrict__ Tlo, int Kd, int Nd)
{
    __shared__ float t[32][33];
    int nb = blockIdx.x * 32, kb = blockIdx.y * 32;
    int tx = threadIdx.x, ty = threadIdx.y;          // (32, 8)
    #pragma unroll
    for (int i = 0; i < 32; i += 8)
        t[ty + i][tx] = W[(size_t)(kb + ty + i) * Nd + nb + tx];
    __syncthreads();
    #pragma unroll
    for (int i = 0; i < 32; i += 8) {
        float v = t[tx][ty + i];
        __nv_bfloat16 h = __float2bfloat16(v);
        float r = v - __bfloat162float(h);
        size_t o = (size_t)(nb + ty + i) * Kd + kb + tx;
        Thi[o] = h;
        Tlo[o] = __float2bfloat16(r);
    }
}

// =====================================================================================
// mma.sync split-bf16 GEMM (R4-proven core). mode 0: fp32 C. mode 1: split bf16 out.
// =====================================================================================
#define GEMM_SMEM (2 * 65536)

__global__ __launch_bounds__(256)
void gemm_tc(const __nv_bfloat16* __restrict__ Ahi, const __nv_bfloat16* __restrict__ Alo,
             const __nv_bfloat16* __restrict__ Bhi, const __nv_bfloat16* __restrict__ Blo,
             float* __restrict__ C, __nv_bfloat16* __restrict__ Chi,
             __nv_bfloat16* __restrict__ Clo, float scale, int mode,
             int M, int N, int K)
{
    extern __shared__ char smem[];
    const uint32_t smem_base = smem_to_u32(smem);
    const int tid = threadIdx.x;
    const int wid = tid >> 5;
    const int lid = tid & 31;
    const int m0 = blockIdx.y * 128;
    const int n0 = blockIdx.x * 128;
    const int warp_m = (wid & 1) * 64;
    const int warp_n = (wid >> 1) * 32;

    float d[4][4][4];
    #pragma unroll
    for (int mi = 0; mi < 4; mi++)
        #pragma unroll
        for (int ni = 0; ni < 4; ni++)
            #pragma unroll
            for (int j = 0; j < 4; j++) d[mi][ni][j] = 0.f;

    const int NCH = K >> 6;

    #pragma unroll
    for (int t = 0; t < 4; t++) {
        const __nv_bfloat16* src = (t == 0) ? Ahi : (t == 1) ? Alo : (t == 2) ? Bhi : Blo;
        const int base_row = (t < 2) ? m0 : n0;
        #pragma unroll
        for (int it = 0; it < 4; it++) {
            int idx = tid + it * 256;
            int row = idx >> 3, seg = idx & 7;
            cp_async16(smem_base + t * 16384 + SMEM_SWIZZLE_128B((uint32_t)(row * 128 + seg * 16)),
                       src + (size_t)(base_row + row) * K + seg * 8);
        }
    }
    CP_COMMIT();
    CP_WAIT0();
    __syncthreads();

    for (int c = 0; c < NCH; c++) {
        const uint32_t sb = smem_base + (c & 1) * 65536;

        if (c + 1 < NCH) {
            const uint32_t nb = smem_base + ((c + 1) & 1) * 65536;
            const int kc = (c + 1) << 6;
            #pragma unroll
            for (int t = 0; t < 4; t++) {
                const __nv_bfloat16* src = (t == 0) ? Ahi : (t == 1) ? Alo : (t == 2) ? Bhi : Blo;
                const int base_row = (t < 2) ? m0 : n0;
                #pragma unroll
                for (int it = 0; it < 4; it++) {
                    int idx = tid + it * 256;
                    int row = idx >> 3, seg = idx & 7;
                    cp_async16(nb + t * 16384 + SMEM_SWIZZLE_128B((uint32_t)(row * 128 + seg * 16)),
                               src + (size_t)(base_row + row) * K + kc + seg * 8);
                }
            }
            CP_COMMIT();
        }

        #pragma unroll
        for (int ks = 0; ks < 4; ks++) {
            uint32_t ah[4][4], al[4][4];
            #pragma unroll
            for (int mi = 0; mi < 4; mi++) {
                uint32_t off = SMEM_SWIZZLE_128B(
                    (uint32_t)((warp_m + mi * 16 + (lid & 15)) * 128 + ks * 32 + ((lid >> 4) & 1) * 16));
                LDSM_X4(ah[mi][0], ah[mi][1], ah[mi][2], ah[mi][3], sb + off);
                LDSM_X4(al[mi][0], al[mi][1], al[mi][2], al[mi][3], sb + 16384 + off);
            }
            uint32_t bh[4][2], bl[4][2];
            #pragma unroll
            for (int pr = 0; pr < 2; pr++) {
                uint32_t off = SMEM_SWIZZLE_128B(
                    (uint32_t)((warp_n + pr * 16 + ((lid >> 4) & 1) * 8 + (lid & 7)) * 128
                               + ks * 32 + ((lid >> 3) & 1) * 16));
                LDSM_X4(bh[pr * 2][0], bh[pr * 2][1], bh[pr * 2 + 1][0], bh[pr * 2 + 1][1],
                        sb + 32768 + off);
                LDSM_X4(bl[pr * 2][0], bl[pr * 2][1], bl[pr * 2 + 1][0], bl[pr * 2 + 1][1],
                        sb + 49152 + off);
            }
            #pragma unroll
            for (int mi = 0; mi < 4; mi++)
                #pragma unroll
                for (int ni = 0; ni < 4; ni++)
                    mma16816(d[mi][ni], ah[mi], bh[ni]);
            #pragma unroll
            for (int mi = 0; mi < 4; mi++)
                #pragma unroll
                for (int ni = 0; ni < 4; ni++)
                    mma16816(d[mi][ni], ah[mi], bl[ni]);
            #pragma unroll
            for (int mi = 0; mi < 4; mi++)
                #pragma unroll
                for (int ni = 0; ni < 4; ni++)
                    mma16816(d[mi][ni], al[mi], bh[ni]);
        }

        if (c + 1 < NCH) {
            CP_WAIT0();
            __syncthreads();
        }
    }

    // ---- epilogue ----
    if (mode == 0) {
        #pragma unroll
        for (int mi = 0; mi < 4; mi++) {
            const int row = m0 + warp_m + mi * 16 + (lid >> 2);
            #pragma unroll
            for (int ni = 0; ni < 4; ni++) {
                const int col = n0 + warp_n + ni * 8 + (lid & 3) * 2;
                *(float2*)(C + (size_t)row * N + col)       = make_float2(d[mi][ni][0], d[mi][ni][1]);
                *(float2*)(C + (size_t)(row + 8) * N + col) = make_float2(d[mi][ni][2], d[mi][ni][3]);
            }
        }
    } else {
        #pragma unroll
        for (int mi = 0; mi < 4; mi++) {
            const int row = m0 + warp_m + mi * 16 + (lid >> 2);
            #pragma unroll
            for (int ni = 0; ni < 4; ni++) {
                const int col = n0 + warp_n + ni * 8 + (lid & 3) * 2;
                float v0 = d[mi][ni][0] * scale, v1 = d[mi][ni][1] * scale;
                float v2 = d[mi][ni][2] * scale, v3 = d[mi][ni][3] * scale;
                uint32_t h01 = pkbf(v0, v1), h23 = pkbf(v2, v3);
                uint32_t l01 = pkbf(v0 - lo2f(h01), v1 - hi2f(h01));
                uint32_t l23 = pkbf(v2 - lo2f(h23), v3 - hi2f(h23));
                *(uint32_t*)(Chi + (size_t)row * N + col)       = h01;
                *(uint32_t*)(Clo + (size_t)row * N + col)       = l01;
                *(uint32_t*)(Chi + (size_t)(row + 8) * N + col) = h23;
                *(uint32_t*)(Clo + (size_t)(row + 8) * N + col) = l23;
            }
        }
    }
}

// =====================================================================================
// Tensor-core flash attention.
// Grid (NN/128, HH, BB), 256 threads (8 warps, each owns m16 of the 128 Q rows).
// KV tiles of 64, cp.async double-buffered. Split-bf16 (3 products) for QK^T and PV.
// P stays in registers (S C-fragment == PV A-fragment layout).
// smem per buffer: KH 8KB | KL 8KB | VH 8KB | VL 8KB. Two buffers = 64 KB.
// =====================================================================================
#define ATTN_SMEM (2 * 32768)

__device__ __forceinline__ void stage_kv(int tid, uint32_t buf,
                                         const __nv_bfloat16* kvh, const __nv_bfloat16* kvl,
                                         int t)
{
    // arrays: 0=KH 1=KL 2=VH 3=VL ; each 64 rows x 64 bf16 (128B rows, SW128)
    #pragma unroll
    for (int a = 0; a < 8; a++) {
        const int arr  = a >> 1;
        const int row  = (a & 1) * 32 + (tid >> 3);
        const int seg  = tid & 7;
        const __nv_bfloat16* base = (arr == 0) ? kvh : (arr == 1) ? kvl
                                  : (arr == 2) ? (kvh + DD) : (kvl + DD);
        cp_async16(buf + arr * 8192 + SMEM_SWIZZLE_128B((uint32_t)(row * 128 + seg * 16)),
                   base + (size_t)(t * 64 + row) * (2 * DD) + seg * 8);
    }
}

__global__ __launch_bounds__(256)
void attn_tc(const __nv_bfloat16* __restrict__ qphi, const __nv_bfloat16* __restrict__ qplo,
             const __nv_bfloat16* __restrict__ kvphi, const __nv_bfloat16* __restrict__ kvplo,
             __nv_bfloat16* __restrict__ aohi, __nv_bfloat16* __restrict__ aolo)
{
    extern __shared__ char smem[];
    const uint32_t smb = smem_to_u32(smem);
    const int tid = threadIdx.x;
    const int wid = tid >> 5;
    const int lid = tid & 31;
    const int b = blockIdx.z, h = blockIdx.y;
    const int q0 = blockIdx.x * 128;
    const int gr = lid >> 2, ci = lid & 3;

    // ---- Q fragments from gmem (loop-invariant). scale 0.125 already folded in. ----
    const size_t qr0 = ((size_t)(b * NN + q0 + wid * 16 + gr)) * DD + h * DHH;
    const size_t qr1 = qr0 + 8 * DD;
    uint32_t qh[4][4], ql[4][4];
    #pragma unroll
    for (int ks = 0; ks < 4; ks++) {
        const int k0 = ks * 16 + ci * 2;
        qh[ks][0] = *(const uint32_t*)(qphi + qr0 + k0);
        qh[ks][1] = *(const uint32_t*)(qphi + qr1 + k0);
        qh[ks][2] = *(const uint32_t*)(qphi + qr0 + k0 + 8);
        qh[ks][3] = *(const uint32_t*)(qphi + qr1 + k0 + 8);
        ql[ks][0] = *(const uint32_t*)(qplo + qr0 + k0);
        ql[ks][1] = *(const uint32_t*)(qplo + qr1 + k0);
        ql[ks][2] = *(const uint32_t*)(qplo + qr0 + k0 + 8);
        ql[ks][3] = *(const uint32_t*)(qplo + qr1 + k0 + 8);
    }

    const __nv_bfloat16* kvh = kvphi + (size_t)(b * NN) * (2 * DD) + h * DHH;
    const __nv_bfloat16* kvl = kvplo + (size_t)(b * NN) * (2 * DD) + h * DHH;

    float oacc[8][4];
    #pragma unroll
    for (int nf = 0; nf < 8; nf++)
        #pragma unroll
        for (int j = 0; j < 4; j++) oacc[nf][j] = 0.f;
    float m0 = -1e30f, m1 = -1e30f, l0 = 0.f, l1 = 0.f;

    stage_kv(tid, smb, kvh, kvl, 0);
    CP_COMMIT();

    for (int t = 0; t < NT; t++) {
        if (t + 1 < NT) {
            stage_kv(tid, smb + ((t + 1) & 1) * 32768, kvh, kvl, t + 1);
            CP_COMMIT();
            CP_WAIT1();
        } else {
            CP_WAIT0();
        }
        __syncthreads();
        const uint32_t kb = smb + (t & 1) * 32768;

        // ---- S = Q K^T : m16 x n64 x k64 per warp, 3 split products ----
        float sacc[8][4];
        #pragma unroll
        for (int nf = 0; nf < 8; nf++)
            #pragma unroll
            for (int j = 0; j < 4; j++) sacc[nf][j] = 0.f;

        #pragma unroll
        for (int ks = 0; ks < 4; ks++) {
            uint32_t bh[8][2], bl[8][2];
            #pragma unroll
            for (int pr = 0; pr < 4; pr++) {
                uint32_t off = SMEM_SWIZZLE_128B(
                    (uint32_t)((pr * 16 + ((lid >> 4) & 1) * 8 + (lid & 7)) * 128
                               + ks * 32 + ((lid >> 3) & 1) * 16));
                LDSM_X4(bh[pr * 2][0], bh[pr * 2][1], bh[pr * 2 + 1][0], bh[pr * 2 + 1][1],
                        kb + off);
                LDSM_X4(bl[pr * 2][0], bl[pr * 2][1], bl[pr * 2 + 1][0], bl[pr * 2 + 1][1],
                        kb + 8192 + off);
            }
            #pragma unroll
            for (int nf = 0; nf < 8; nf++) mma16816(sacc[nf], qh[ks], bh[nf]);
            #pragma unroll
            for (int nf = 0; nf < 8; nf++) mma16816(sacc[nf], qh[ks], bl[nf]);
            #pragma unroll
            for (int nf = 0; nf < 8; nf++) mma16816(sacc[nf], ql[ks], bh[nf]);
        }

        // ---- online softmax (rows gr, gr+8; quad lanes share a row) ----
        float mt0 = -1e30f, mt1 = -1e30f;
        #pragma unroll
        for (int nf = 0; nf < 8; nf++) {
            mt0 = fmaxf(mt0, fmaxf(sacc[nf][0], sacc[nf][1]));
            mt1 = fmaxf(mt1, fmaxf(sacc[nf][2], sacc[nf][3]));
        }
        mt0 = fmaxf(mt0, __shfl_xor_sync(0xffffffffu, mt0, 1));
        mt0 = fmaxf(mt0, __shfl_xor_sync(0xffffffffu, mt0, 2));
        mt1 = fmaxf(mt1, __shfl_xor_sync(0xffffffffu, mt1, 1));
        mt1 = fmaxf(mt1, __shfl_xor_sync(0xffffffffu, mt1, 2));
        const float mn0 = fmaxf(m0, mt0), mn1 = fmaxf(m1, mt1);
        const float al0 = __expf(m0 - mn0), al1 = __expf(m1 - mn1);
        m0 = mn0; m1 = mn1;
        float rs0 = 0.f, rs1 = 0.f;
        #pragma unroll
        for (int nf = 0; nf < 8; nf++) {
            sacc[nf][0] = __expf(sacc[nf][0] - mn0);
            sacc[nf][1] = __expf(sacc[nf][1] - mn0);
            sacc[nf][2] = __expf(sacc[nf][2] - mn1);
            sacc[nf][3] = __expf(sacc[nf][3] - mn1);
            rs0 += sacc[nf][0] + sacc[nf][1];
            rs1 += sacc[nf][2] + sacc[nf][3];
        }
        rs0 += __shfl_xor_sync(0xffffffffu, rs0, 1);
        rs0 += __shfl_xor_sync(0xffffffffu, rs0, 2);
        rs1 += __shfl_xor_sync(0xffffffffu, rs1, 1);
        rs1 += __shfl_xor_sync(0xffffffffu, rs1, 2);
        l0 = l0 * al0 + rs0;
        l1 = l1 * al1 + rs1;
        #pragma unroll
        for (int nf = 0; nf < 8; nf++) {
            oacc[nf][0] *= al0; oacc[nf][1] *= al0;
            oacc[nf][2] *= al1; oacc[nf][3] *= al1;
        }

        // ---- O += P V : m16 x n64(d) x k64(kv); P from registers, split hi/lo ----
        #pragma unroll
        for (int ks = 0; ks < 4; ks++) {
            // A fragments from S accum frags 2ks, 2ks+1
            uint32_t aPh[4], aPl[4];
            {
                const float c0 = sacc[2 * ks][0],     c1 = sacc[2 * ks][1];
                const float c2 = sacc[2 * ks][2],     c3 = sacc[2 * ks][3];
                const float e0 = sacc[2 * ks + 1][0], e1 = sacc[2 * ks + 1][1];
                const float e2 = sacc[2 * ks + 1][2], e3 = sacc[2 * ks + 1][3];
                aPh[0] = pkbf(c0, c1); aPh[1] = pkbf(c2, c3);
                aPh[2] = pkbf(e0, e1); aPh[3] = pkbf(e2, e3);
                aPl[0] = pkbf(c0 - lo2f(aPh[0]), c1 - hi2f(aPh[0]));
                aPl[1] = pkbf(c2 - lo2f(aPh[1]), c3 - hi2f(aPh[1]));
                aPl[2] = pkbf(e0 - lo2f(aPh[2]), e1 - hi2f(aPh[2]));
                aPl[3] = pkbf(e2 - lo2f(aPh[3]), e3 - hi2f(aPh[3]));
            }
            uint32_t vh[8][2], vl[8][2];
            #pragma unroll
            for (int nfp = 0; nfp < 4; nfp++) {
                uint32_t off = SMEM_SWIZZLE_128B(
                    (uint32_t)((ks * 16 + ((lid >> 3) & 1) * 8 + (lid & 7)) * 128
                               + (2 * nfp + ((lid >> 4) & 1)) * 16));
                LDSM_X4_T(vh[2 * nfp][0], vh[2 * nfp][1], vh[2 * nfp + 1][0], vh[2 * nfp + 1][1],
                          kb + 16384 + off);
                LDSM_X4_T(vl[2 * nfp][0], vl[2 * nfp][1], vl[2 * nfp + 1][0], vl[2 * nfp + 1][1],
                          kb + 24576 + off);
            }
            #pragma unroll
            for (int nf = 0; nf < 8; nf++) mma16816(oacc[nf], aPh, vh[nf]);
            #pragma unroll
            for (int nf = 0; nf < 8; nf++) mma16816(oacc[nf], aPh, vl[nf]);
            #pragma unroll
            for (int nf = 0; nf < 8; nf++) mma16816(oacc[nf], aPl, vh[nf]);
        }
        __syncthreads();
    }

    // ---- epilogue: normalize, split to bf16 hi/lo, write head-merged ao ----
    const float inv0 = 1.0f / l0, inv1 = 1.0f / l1;
    const size_t or0 = ((size_t)(b * NN + q0 + wid * 16 + gr)) * DD + h * DHH;
    const size_t or1 = or0 + 8 * DD;
    #pragma unroll
    for (int nf = 0; nf < 8; nf++) {
        const int col = nf * 8 + ci * 2;
        float v0 = oacc[nf][0] * inv0, v1 = oacc[nf][1] * inv0;
        float v2 = oacc[nf][2] * inv1, v3 = oacc[nf][3] * inv1;
        uint32_t h01 = pkbf(v0, v1), h23 = pkbf(v2, v3);
        uint32_t l01 = pkbf(v0 - lo2f(h01), v1 - hi2f(h01));
        uint32_t l23 = pkbf(v2 - lo2f(h23), v3 - hi2f(h23));
        *(uint32_t*)(aohi + or0 + col) = h01;
        *(uint32_t*)(aolo + or0 + col) = l01;
        *(uint32_t*)(aohi + or1 + col) = h23;
        *(uint32_t*)(aolo + or1 + col) = l23;
    }
}

// =====================================================================================
// Launch
// =====================================================================================
extern "C" void kernel_launch(void* const* d_in, const int* in_sizes, int n_in,
                              void* d_out, int out_size)
{
    const float* q    = (const float*)d_in[0];
    const float* kv   = (const float*)d_in[1];
    const float* Wq   = (const float*)d_in[2];
    const float* Wkv  = (const float*)d_in[3];
    const float* Wout = (const float*)d_in[4];
    float* out = (float*)d_out;

    __nv_bfloat16 *ahi, *alo, *qphi, *qplo, *kvphi, *kvplo, *wthi, *wtlo;
    cudaGetSymbolAddress((void**)&ahi,   g_ahi);
    cudaGetSymbolAddress((void**)&alo,   g_alo);
    cudaGetSymbolAddress((void**)&qphi,  g_qphi);
    cudaGetSymbolAddress((void**)&qplo,  g_qplo);
    cudaGetSymbolAddress((void**)&kvphi, g_kvphi);
    cudaGetSymbolAddress((void**)&kvplo, g_kvplo);
    cudaGetSymbolAddress((void**)&wthi,  g_wthi);
    cudaGetSymbolAddress((void**)&wtlo,  g_wtlo);

    const int M = BB * NN;              // 4096
    const int nact = M * DD;

    cudaFuncSetAttribute(gemm_tc, cudaFuncAttributeMaxDynamicSharedMemorySize, GEMM_SMEM);
    cudaFuncSetAttribute(attn_tc, cudaFuncAttributeMaxDynamicSharedMemorySize, ATTN_SMEM);

    dim3 tb(256);
    dim3 tt(32, 8);

    // ---- 1) qp = (q @ Wq) * 0.125, split epilogue ----
    split_act<<<nact / 4 / 256, tb>>>(q, ahi, alo, nact);
    transpose_split<<<dim3(DD / 32, DD / 32), tt>>>(Wq, wthi, wtlo, DD, DD);
    gemm_tc<<<dim3(DD / 128, M / 128), tb, GEMM_SMEM>>>(
        ahi, alo, wthi, wtlo, nullptr, qphi, qplo, 0.125f, 1, M, DD, DD);

    // ---- 2) kvp = kv @ Wkv, split epilogue ----
    split_act<<<nact / 4 / 256, tb>>>(kv, ahi, alo, nact);
    transpose_split<<<dim3((2 * DD) / 32, DD / 32), tt>>>(Wkv, wthi, wtlo, DD, 2 * DD);
    gemm_tc<<<dim3((2 * DD) / 128, M / 128), tb, GEMM_SMEM>>>(
        ahi, alo, wthi, wtlo, nullptr, kvphi, kvplo, 1.0f, 1, M, 2 * DD, DD);

    // ---- 3) tensor-core flash attention -> ao split (reuses ahi/alo) ----
    attn_tc<<<dim3(NN / 128, HH, BB), tb, ATTN_SMEM>>>(qphi, qplo, kvphi, kvplo, ahi, alo);

    // ---- 4) out = ao @ Wout, fp32 epilogue ----
    transpose_split<<<dim3(DD / 32, DD / 32), tt>>>(Wout, wthi, wtlo, DD, DD);
    gemm_tc<<<dim3(DD / 128, M / 128), tb, GEMM_SMEM>>>(
        ahi, alo, wthi, wtlo, out, nullptr, nullptr, 1.0f, 0, M, DD, DD);
}

// round 8
// speedup vs baseline: 3.3295x; 1.1440x over previous
#include <cuda_runtime.h>
#include <cuda_bf16.h>
#include <cstdint>

// Problem constants (fixed shapes per reference)
#define BB   2
#define NN   2048
#define DD   1024
#define HH   16
#define DHH  64
#define NT   (NN / 64)   // 32 KV tiles of 64

// ---------------- scratch (__device__ globals; allocation is forbidden) ----------------
__device__ __align__(16) __nv_bfloat16 g_ahi [BB * NN * DD];     // act split hi (also ao hi)
__device__ __align__(16) __nv_bfloat16 g_alo [BB * NN * DD];     // act split lo (also ao lo)
__device__ __align__(16) __nv_bfloat16 g_qphi[BB * NN * DD];     // qp split hi (0.125 folded)
__device__ __align__(16) __nv_bfloat16 g_qplo[BB * NN * DD];
__device__ __align__(16) __nv_bfloat16 g_kvphi[BB * NN * 2 * DD];
__device__ __align__(16) __nv_bfloat16 g_kvplo[BB * NN * 2 * DD];
__device__ __align__(16) __nv_bfloat16 g_wthi[2 * DD * DD];      // weight^T split hi [N,K]
__device__ __align__(16) __nv_bfloat16 g_wtlo[2 * DD * DD];

// ---------------- helpers ----------------
__device__ __forceinline__ uint32_t smem_to_u32(const void* p) {
    uint32_t a;
    asm("{ .reg .u64 t; cvta.to.shared.u64 t, %1; cvt.u32.u64 %0, t; }" : "=r"(a) : "l"(p));
    return a;
}
#define SMEM_SWIZZLE_128B(off) ((off) ^ (((off) >> 3) & 0x70))

__device__ __forceinline__ void cp_async16(uint32_t s, const void* g) {
    asm volatile("cp.async.cg.shared.global [%0], [%1], 16;" :: "r"(s), "l"(g));
}
#define CP_COMMIT() asm volatile("cp.async.commit_group;" ::: "memory")
#define CP_WAIT0()  asm volatile("cp.async.wait_group 0;" ::: "memory")
#define CP_WAIT1()  asm volatile("cp.async.wait_group 1;" ::: "memory")

#define LDSM_X4(r0, r1, r2, r3, addr) \
    asm volatile("ldmatrix.sync.aligned.m8n8.x4.shared.b16 {%0,%1,%2,%3}, [%4];" \
                 : "=r"(r0), "=r"(r1), "=r"(r2), "=r"(r3) : "r"(addr))
#define LDSM_X4_T(r0, r1, r2, r3, addr) \
    asm volatile("ldmatrix.sync.aligned.m8n8.x4.trans.shared.b16 {%0,%1,%2,%3}, [%4];" \
                 : "=r"(r0), "=r"(r1), "=r"(r2), "=r"(r3) : "r"(addr))

__device__ __forceinline__ void mma16816(float* d, const uint32_t* a, const uint32_t* b) {
    asm volatile("mma.sync.aligned.m16n8k16.row.col.f32.bf16.bf16.f32 "
        "{%0,%1,%2,%3},{%4,%5,%6,%7},{%8,%9},{%0,%1,%2,%3};"
        : "+f"(d[0]), "+f"(d[1]), "+f"(d[2]), "+f"(d[3])
        : "r"(a[0]), "r"(a[1]), "r"(a[2]), "r"(a[3]), "r"(b[0]), "r"(b[1]));
}

// pack two fp32 -> bf16x2 (lo element in low 16 bits)
__device__ __forceinline__ uint32_t pkbf(float lo, float hi) {
    uint32_t r; asm("cvt.rn.bf16x2.f32 %0, %1, %2;" : "=r"(r) : "f"(hi), "f"(lo)); return r;
}
__device__ __forceinline__ float lo2f(uint32_t u) { return __uint_as_float(u << 16); }
__device__ __forceinline__ float hi2f(uint32_t u) { return __uint_as_float(u & 0xffff0000u); }

// =====================================================================================
// Prep kernels
// =====================================================================================
__global__ __launch_bounds__(256)
void split_act(const float* __restrict__ x, __nv_bfloat16* __restrict__ hi,
               __nv_bfloat16* __restrict__ lo, int n)
{
    int i = (blockIdx.x * 256 + threadIdx.x) * 4;
    if (i >= n) return;
    float4 v = *(const float4*)(x + i);
    float vv[4] = { v.x, v.y, v.z, v.w };
    uint32_t h01 = pkbf(vv[0], vv[1]), h23 = pkbf(vv[2], vv[3]);
    uint32_t l01 = pkbf(vv[0] - lo2f(h01), vv[1] - hi2f(h01));
    uint32_t l23 = pkbf(vv[2] - lo2f(h23), vv[3] - hi2f(h23));
    *(uint32_t*)(hi + i)     = h01;
    *(uint32_t*)(hi + i + 2) = h23;
    *(uint32_t*)(lo + i)     = l01;
    *(uint32_t*)(lo + i + 2) = l23;
}

// W[K,N] row-major  ->  Wt_hi/lo[N,K] (K-major)
__global__ __launch_bounds__(256)
void transpose_split(const float* __restrict__ W, __nv_bfloat16* __restrict__ Thi,
                     __nv_bfloat16* __restrict__ Tlo, int Kd, int Nd)
{
    __shared__ float t[32][33];
    int nb = blockIdx.x * 32, kb = blockIdx.y * 32;
    int tx = threadIdx.x, ty = threadIdx.y;          // (32, 8)
    #pragma unroll
    for (int i = 0; i < 32; i += 8)
        t[ty + i][tx] = W[(size_t)(kb + ty + i) * Nd + nb + tx];
    __syncthreads();
    #pragma unroll
    for (int i = 0; i < 32; i += 8) {
        float v = t[tx][ty + i];
        __nv_bfloat16 h = __float2bfloat16(v);
        float r = v - __bfloat162float(h);
        size_t o = (size_t)(nb + ty + i) * Kd + kb + tx;
        Thi[o] = h;
        Tlo[o] = __float2bfloat16(r);
    }
}

// =====================================================================================
// mma.sync split-bf16 GEMM v2: CTA tile 128(M) x 256(N), BK=64, 2-stage (192KB smem).
// 8 warps 2(m) x 4(n), warp tile 64x64 -> 4 m16 x 8 n8 fragments.
// 3 HMMA products per fragment per K16 step (hi*hi + hi*lo + lo*hi).
// Stage layout: Ahi 16KB | Alo 16KB | Bhi 32KB | Blo 32KB = 96KB. Stage stride 98304.
// mode 0: fp32 C out. mode 1: split bf16 (Chi/Clo) out with scale folded.
// =====================================================================================
#define GEMM_STAGE 98304
#define GEMM_SMEM  (2 * GEMM_STAGE)

__global__ __launch_bounds__(256)
void gemm_tc(const __nv_bfloat16* __restrict__ Ahi, const __nv_bfloat16* __restrict__ Alo,
             const __nv_bfloat16* __restrict__ Bhi, const __nv_bfloat16* __restrict__ Blo,
             float* __restrict__ C, __nv_bfloat16* __restrict__ Chi,
             __nv_bfloat16* __restrict__ Clo, float scale, int mode,
             int M, int N, int K)
{
    extern __shared__ char smem[];
    const uint32_t smem_base = smem_to_u32(smem);
    const int tid = threadIdx.x;
    const int wid = tid >> 5;
    const int lid = tid & 31;
    const int m0 = blockIdx.y * 128;
    const int n0 = blockIdx.x * 256;
    const int warp_m = (wid & 1) * 64;
    const int warp_n = (wid >> 1) * 64;

    float d[4][8][4];
    #pragma unroll
    for (int mi = 0; mi < 4; mi++)
        #pragma unroll
        for (int ni = 0; ni < 8; ni++)
            #pragma unroll
            for (int j = 0; j < 4; j++) d[mi][ni][j] = 0.f;

    const int NCH = K >> 6;                            // 16 chunks of K=64

    // ---- stage chunk 0 ----
    {
        const uint32_t sb = smem_base;
        #pragma unroll
        for (int t = 0; t < 2; t++) {
            const __nv_bfloat16* src = t ? Alo : Ahi;
            #pragma unroll
            for (int it = 0; it < 4; it++) {
                int idx = tid + it * 256;
                int row = idx >> 3, seg = idx & 7;
                cp_async16(sb + t * 16384 + SMEM_SWIZZLE_128B((uint32_t)(row * 128 + seg * 16)),
                           src + (size_t)(m0 + row) * K + seg * 8);
            }
        }
        #pragma unroll
        for (int t = 0; t < 2; t++) {
            const __nv_bfloat16* src = t ? Blo : Bhi;
            #pragma unroll
            for (int it = 0; it < 8; it++) {
                int idx = tid + it * 256;
                int row = idx >> 3, seg = idx & 7;
                cp_async16(sb + 32768 + t * 32768 + SMEM_SWIZZLE_128B((uint32_t)(row * 128 + seg * 16)),
                           src + (size_t)(n0 + row) * K + seg * 8);
            }
        }
    }
    CP_COMMIT();
    CP_WAIT0();
    __syncthreads();

    for (int c = 0; c < NCH; c++) {
        const uint32_t sb = smem_base + (c & 1) * GEMM_STAGE;

        if (c + 1 < NCH) {
            const uint32_t nb = smem_base + ((c + 1) & 1) * GEMM_STAGE;
            const int kc = (c + 1) << 6;
            #pragma unroll
            for (int t = 0; t < 2; t++) {
                const __nv_bfloat16* src = t ? Alo : Ahi;
                #pragma unroll
                for (int it = 0; it < 4; it++) {
                    int idx = tid + it * 256;
                    int row = idx >> 3, seg = idx & 7;
                    cp_async16(nb + t * 16384 + SMEM_SWIZZLE_128B((uint32_t)(row * 128 + seg * 16)),
                               src + (size_t)(m0 + row) * K + kc + seg * 8);
                }
            }
            #pragma unroll
            for (int t = 0; t < 2; t++) {
                const __nv_bfloat16* src = t ? Blo : Bhi;
                #pragma unroll
                for (int it = 0; it < 8; it++) {
                    int idx = tid + it * 256;
                    int row = idx >> 3, seg = idx & 7;
                    cp_async16(nb + 32768 + t * 32768 + SMEM_SWIZZLE_128B((uint32_t)(row * 128 + seg * 16)),
                               src + (size_t)(n0 + row) * K + kc + seg * 8);
                }
            }
            CP_COMMIT();
        }

        #pragma unroll
        for (int ks = 0; ks < 4; ks++) {
            uint32_t ah[4][4], al[4][4];
            #pragma unroll
            for (int mi = 0; mi < 4; mi++) {
                uint32_t off = SMEM_SWIZZLE_128B(
                    (uint32_t)((warp_m + mi * 16 + (lid & 15)) * 128 + ks * 32 + ((lid >> 4) & 1) * 16));
                LDSM_X4(ah[mi][0], ah[mi][1], ah[mi][2], ah[mi][3], sb + off);
                LDSM_X4(al[mi][0], al[mi][1], al[mi][2], al[mi][3], sb + 16384 + off);
            }
            uint32_t bh[8][2], bl[8][2];
            #pragma unroll
            for (int pr = 0; pr < 4; pr++) {
                uint32_t off = SMEM_SWIZZLE_128B(
                    (uint32_t)((warp_n + pr * 16 + ((lid >> 4) & 1) * 8 + (lid & 7)) * 128
                               + ks * 32 + ((lid >> 3) & 1) * 16));
                LDSM_X4(bh[pr * 2][0], bh[pr * 2][1], bh[pr * 2 + 1][0], bh[pr * 2 + 1][1],
                        sb + 32768 + off);
                LDSM_X4(bl[pr * 2][0], bl[pr * 2][1], bl[pr * 2 + 1][0], bl[pr * 2 + 1][1],
                        sb + 65536 + off);
            }
            #pragma unroll
            for (int mi = 0; mi < 4; mi++)
                #pragma unroll
                for (int ni = 0; ni < 8; ni++)
                    mma16816(d[mi][ni], ah[mi], bh[ni]);
            #pragma unroll
            for (int mi = 0; mi < 4; mi++)
                #pragma unroll
                for (int ni = 0; ni < 8; ni++)
                    mma16816(d[mi][ni], ah[mi], bl[ni]);
            #pragma unroll
            for (int mi = 0; mi < 4; mi++)
                #pragma unroll
                for (int ni = 0; ni < 8; ni++)
                    mma16816(d[mi][ni], al[mi], bh[ni]);
        }

        if (c + 1 < NCH) {
            CP_WAIT0();
            __syncthreads();
        }
    }

    // ---- epilogue ----
    if (mode == 0) {
        #pragma unroll
        for (int mi = 0; mi < 4; mi++) {
            const int row = m0 + warp_m + mi * 16 + (lid >> 2);
            #pragma unroll
            for (int ni = 0; ni < 8; ni++) {
                const int col = n0 + warp_n + ni * 8 + (lid & 3) * 2;
                *(float2*)(C + (size_t)row * N + col)       = make_float2(d[mi][ni][0], d[mi][ni][1]);
                *(float2*)(C + (size_t)(row + 8) * N + col) = make_float2(d[mi][ni][2], d[mi][ni][3]);
            }
        }
    } else {
        #pragma unroll
        for (int mi = 0; mi < 4; mi++) {
            const int row = m0 + warp_m + mi * 16 + (lid >> 2);
            #pragma unroll
            for (int ni = 0; ni < 8; ni++) {
                const int col = n0 + warp_n + ni * 8 + (lid & 3) * 2;
                float v0 = d[mi][ni][0] * scale, v1 = d[mi][ni][1] * scale;
                float v2 = d[mi][ni][2] * scale, v3 = d[mi][ni][3] * scale;
                uint32_t h01 = pkbf(v0, v1), h23 = pkbf(v2, v3);
                uint32_t l01 = pkbf(v0 - lo2f(h01), v1 - hi2f(h01));
                uint32_t l23 = pkbf(v2 - lo2f(h23), v3 - hi2f(h23));
                *(uint32_t*)(Chi + (size_t)row * N + col)       = h01;
                *(uint32_t*)(Clo + (size_t)row * N + col)       = l01;
                *(uint32_t*)(Chi + (size_t)(row + 8) * N + col) = h23;
                *(uint32_t*)(Clo + (size_t)(row + 8) * N + col) = l23;
            }
        }
    }
}

// =====================================================================================
// Tensor-core flash attention v2: 128-thread CTAs (4 warps, 64 Q rows) so 2-3 CTAs
// co-reside per SM and softmax of one CTA overlaps MMAs of another.
// Grid (NN/64, HH, BB). KV tiles of 64, cp.async double-buffered (2 x 32KB smem).
// Warp-level math identical to the R6-proven kernel.
// =====================================================================================
#define ATTN_SMEM (2 * 32768)

__device__ __forceinline__ void stage_kv(int tid, uint32_t buf,
                                         const __nv_bfloat16* kvh, const __nv_bfloat16* kvl,
                                         int t)
{
    // arrays: 0=KH 1=KL 2=VH 3=VL ; each 64 rows x 64 bf16 (128B rows, SW128)
    #pragma unroll
    for (int a = 0; a < 4; a++) {
        const __nv_bfloat16* base = (a == 0) ? kvh : (a == 1) ? kvl
                                  : (a == 2) ? (kvh + DD) : (kvl + DD);
        #pragma unroll
        for (int it = 0; it < 4; it++) {
            int idx = tid + it * 128;
            int row = idx >> 3, seg = idx & 7;
            cp_async16(buf + a * 8192 + SMEM_SWIZZLE_128B((uint32_t)(row * 128 + seg * 16)),
                       base + (size_t)(t * 64 + row) * (2 * DD) + seg * 8);
        }
    }
}

__global__ __launch_bounds__(128)
void attn_tc(const __nv_bfloat16* __restrict__ qphi, const __nv_bfloat16* __restrict__ qplo,
             const __nv_bfloat16* __restrict__ kvphi, const __nv_bfloat16* __restrict__ kvplo,
             __nv_bfloat16* __restrict__ aohi, __nv_bfloat16* __restrict__ aolo)
{
    extern __shared__ char smem[];
    const uint32_t smb = smem_to_u32(smem);
    const int tid = threadIdx.x;
    const int wid = tid >> 5;          // 0..3
    const int lid = tid & 31;
    const int b = blockIdx.z, h = blockIdx.y;
    const int q0 = blockIdx.x * 64;
    const int gr = lid >> 2, ci = lid & 3;

    // ---- Q fragments from gmem (loop-invariant). scale 0.125 already folded in. ----
    const size_t qr0 = ((size_t)(b * NN + q0 + wid * 16 + gr)) * DD + h * DHH;
    const size_t qr1 = qr0 + 8 * DD;
    uint32_t qh[4][4], ql[4][4];
    #pragma unroll
    for (int ks = 0; ks < 4; ks++) {
        const int k0 = ks * 16 + ci * 2;
        qh[ks][0] = *(const uint32_t*)(qphi + qr0 + k0);
        qh[ks][1] = *(const uint32_t*)(qphi + qr1 + k0);
        qh[ks][2] = *(const uint32_t*)(qphi + qr0 + k0 + 8);
        qh[ks][3] = *(const uint32_t*)(qphi + qr1 + k0 + 8);
        ql[ks][0] = *(const uint32_t*)(qplo + qr0 + k0);
        ql[ks][1] = *(const uint32_t*)(qplo + qr1 + k0);
        ql[ks][2] = *(const uint32_t*)(qplo + qr0 + k0 + 8);
        ql[ks][3] = *(const uint32_t*)(qplo + qr1 + k0 + 8);
    }

    const __nv_bfloat16* kvh = kvphi + (size_t)(b * NN) * (2 * DD) + h * DHH;
    const __nv_bfloat16* kvl = kvplo + (size_t)(b * NN) * (2 * DD) + h * DHH;

    float oacc[8][4];
    #pragma unroll
    for (int nf = 0; nf < 8; nf++)
        #pragma unroll
        for (int j = 0; j < 4; j++) oacc[nf][j] = 0.f;
    float m0 = -1e30f, m1 = -1e30f, l0 = 0.f, l1 = 0.f;

    stage_kv(tid, smb, kvh, kvl, 0);
    CP_COMMIT();

    for (int t = 0; t < NT; t++) {
        if (t + 1 < NT) {
            stage_kv(tid, smb + ((t + 1) & 1) * 32768, kvh, kvl, t + 1);
            CP_COMMIT();
            CP_WAIT1();
        } else {
            CP_WAIT0();
        }
        __syncthreads();
        const uint32_t kb = smb + (t & 1) * 32768;

        // ---- S = Q K^T : m16 x n64 x k64 per warp, 3 split products ----
        float sacc[8][4];
        #pragma unroll
        for (int nf = 0; nf < 8; nf++)
            #pragma unroll
            for (int j = 0; j < 4; j++) sacc[nf][j] = 0.f;

        #pragma unroll
        for (int ks = 0; ks < 4; ks++) {
            uint32_t bh[8][2], bl[8][2];
            #pragma unroll
            for (int pr = 0; pr < 4; pr++) {
                uint32_t off = SMEM_SWIZZLE_128B(
                    (uint32_t)((pr * 16 + ((lid >> 4) & 1) * 8 + (lid & 7)) * 128
                               + ks * 32 + ((lid >> 3) & 1) * 16));
                LDSM_X4(bh[pr * 2][0], bh[pr * 2][1], bh[pr * 2 + 1][0], bh[pr * 2 + 1][1],
                        kb + off);
                LDSM_X4(bl[pr * 2][0], bl[pr * 2][1], bl[pr * 2 + 1][0], bl[pr * 2 + 1][1],
                        kb + 8192 + off);
            }
            #pragma unroll
            for (int nf = 0; nf < 8; nf++) mma16816(sacc[nf], qh[ks], bh[nf]);
            #pragma unroll
            for (int nf = 0; nf < 8; nf++) mma16816(sacc[nf], qh[ks], bl[nf]);
            #pragma unroll
            for (int nf = 0; nf < 8; nf++) mma16816(sacc[nf], ql[ks], bh[nf]);
        }

        // ---- online softmax (rows gr, gr+8; quad lanes share a row) ----
        float mt0 = -1e30f, mt1 = -1e30f;
        #pragma unroll
        for (int nf = 0; nf < 8; nf++) {
            mt0 = fmaxf(mt0, fmaxf(sacc[nf][0], sacc[nf][1]));
            mt1 = fmaxf(mt1, fmaxf(sacc[nf][2], sacc[nf][3]));
        }
        mt0 = fmaxf(mt0, __shfl_xor_sync(0xffffffffu, mt0, 1));
        mt0 = fmaxf(mt0, __shfl_xor_sync(0xffffffffu, mt0, 2));
        mt1 = fmaxf(mt1, __shfl_xor_sync(0xffffffffu, mt1, 1));
        mt1 = fmaxf(mt1, __shfl_xor_sync(0xffffffffu, mt1, 2));
        const float mn0 = fmaxf(m0, mt0), mn1 = fmaxf(m1, mt1);
        const float al0 = __expf(m0 - mn0), al1 = __expf(m1 - mn1);
        m0 = mn0; m1 = mn1;
        float rs0 = 0.f, rs1 = 0.f;
        #pragma unroll
        for (int nf = 0; nf < 8; nf++) {
            sacc[nf][0] = __expf(sacc[nf][0] - mn0);
            sacc[nf][1] = __expf(sacc[nf][1] - mn0);
            sacc[nf][2] = __expf(sacc[nf][2] - mn1);
            sacc[nf][3] = __expf(sacc[nf][3] - mn1);
            rs0 += sacc[nf][0] + sacc[nf][1];
            rs1 += sacc[nf][2] + sacc[nf][3];
        }
        rs0 += __shfl_xor_sync(0xffffffffu, rs0, 1);
        rs0 += __shfl_xor_sync(0xffffffffu, rs0, 2);
        rs1 += __shfl_xor_sync(0xffffffffu, rs1, 1);
        rs1 += __shfl_xor_sync(0xffffffffu, rs1, 2);
        l0 = l0 * al0 + rs0;
        l1 = l1 * al1 + rs1;
        #pragma unroll
        for (int nf = 0; nf < 8; nf++) {
            oacc[nf][0] *= al0; oacc[nf][1] *= al0;
            oacc[nf][2] *= al1; oacc[nf][3] *= al1;
        }

        // ---- O += P V : m16 x n64(d) x k64(kv); P from registers, split hi/lo ----
        #pragma unroll
        for (int ks = 0; ks < 4; ks++) {
            uint32_t aPh[4], aPl[4];
            {
                const float c0 = sacc[2 * ks][0],     c1 = sacc[2 * ks][1];
                const float c2 = sacc[2 * ks][2],     c3 = sacc[2 * ks][3];
                const float e0 = sacc[2 * ks + 1][0], e1 = sacc[2 * ks + 1][1];
                const float e2 = sacc[2 * ks + 1][2], e3 = sacc[2 * ks + 1][3];
                aPh[0] = pkbf(c0, c1); aPh[1] = pkbf(c2, c3);
                aPh[2] = pkbf(e0, e1); aPh[3] = pkbf(e2, e3);
                aPl[0] = pkbf(c0 - lo2f(aPh[0]), c1 - hi2f(aPh[0]));
                aPl[1] = pkbf(c2 - lo2f(aPh[1]), c3 - hi2f(aPh[1]));
                aPl[2] = pkbf(e0 - lo2f(aPh[2]), e1 - hi2f(aPh[2]));
                aPl[3] = pkbf(e2 - lo2f(aPh[3]), e3 - hi2f(aPh[3]));
            }
            uint32_t vh[8][2], vl[8][2];
            #pragma unroll
            for (int nfp = 0; nfp < 4; nfp++) {
                uint32_t off = SMEM_SWIZZLE_128B(
                    (uint32_t)((ks * 16 + ((lid >> 3) & 1) * 8 + (lid & 7)) * 128
                               + (2 * nfp + ((lid >> 4) & 1)) * 16));
                LDSM_X4_T(vh[2 * nfp][0], vh[2 * nfp][1], vh[2 * nfp + 1][0], vh[2 * nfp + 1][1],
                          kb + 16384 + off);
                LDSM_X4_T(vl[2 * nfp][0], vl[2 * nfp][1], vl[2 * nfp + 1][0], vl[2 * nfp + 1][1],
                          kb + 24576 + off);
            }
            #pragma unroll
            for (int nf = 0; nf < 8; nf++) mma16816(oacc[nf], aPh, vh[nf]);
            #pragma unroll
            for (int nf = 0; nf < 8; nf++) mma16816(oacc[nf], aPh, vl[nf]);
            #pragma unroll
            for (int nf = 0; nf < 8; nf++) mma16816(oacc[nf], aPl, vh[nf]);
        }
        __syncthreads();
    }

    // ---- epilogue: normalize, split to bf16 hi/lo, write head-merged ao ----
    const float inv0 = 1.0f / l0, inv1 = 1.0f / l1;
    const size_t or0 = ((size_t)(b * NN + q0 + wid * 16 + gr)) * DD + h * DHH;
    const size_t or1 = or0 + 8 * DD;
    #pragma unroll
    for (int nf = 0; nf < 8; nf++) {
        const int col = nf * 8 + ci * 2;
        float v0 = oacc[nf][0] * inv0, v1 = oacc[nf][1] * inv0;
        float v2 = oacc[nf][2] * inv1, v3 = oacc[nf][3] * inv1;
        uint32_t h01 = pkbf(v0, v1), h23 = pkbf(v2, v3);
        uint32_t l01 = pkbf(v0 - lo2f(h01), v1 - hi2f(h01));
        uint32_t l23 = pkbf(v2 - lo2f(h23), v3 - hi2f(h23));
        *(uint32_t*)(aohi + or0 + col) = h01;
        *(uint32_t*)(aolo + or0 + col) = l01;
        *(uint32_t*)(aohi + or1 + col) = h23;
        *(uint32_t*)(aolo + or1 + col) = l23;
    }
}

// =====================================================================================
// Launch
// =====================================================================================
extern "C" void kernel_launch(void* const* d_in, const int* in_sizes, int n_in,
                              void* d_out, int out_size)
{
    const float* q    = (const float*)d_in[0];
    const float* kv   = (const float*)d_in[1];
    const float* Wq   = (const float*)d_in[2];
    const float* Wkv  = (const float*)d_in[3];
    const float* Wout = (const float*)d_in[4];
    float* out = (float*)d_out;

    __nv_bfloat16 *ahi, *alo, *qphi, *qplo, *kvphi, *kvplo, *wthi, *wtlo;
    cudaGetSymbolAddress((void**)&ahi,   g_ahi);
    cudaGetSymbolAddress((void**)&alo,   g_alo);
    cudaGetSymbolAddress((void**)&qphi,  g_qphi);
    cudaGetSymbolAddress((void**)&qplo,  g_qplo);
    cudaGetSymbolAddress((void**)&kvphi, g_kvphi);
    cudaGetSymbolAddress((void**)&kvplo, g_kvplo);
    cudaGetSymbolAddress((void**)&wthi,  g_wthi);
    cudaGetSymbolAddress((void**)&wtlo,  g_wtlo);

    const int M = BB * NN;              // 4096
    const int nact = M * DD;

    cudaFuncSetAttribute(gemm_tc, cudaFuncAttributeMaxDynamicSharedMemorySize, GEMM_SMEM);
    cudaFuncSetAttribute(attn_tc, cudaFuncAttributeMaxDynamicSharedMemorySize, ATTN_SMEM);

    dim3 tb(256);
    dim3 tt(32, 8);

    // ---- 1) qp = (q @ Wq) * 0.125, split epilogue ----
    split_act<<<nact / 4 / 256, tb>>>(q, ahi, alo, nact);
    transpose_split<<<dim3(DD / 32, DD / 32), tt>>>(Wq, wthi, wtlo, DD, DD);
    gemm_tc<<<dim3(DD / 256, M / 128), tb, GEMM_SMEM>>>(
        ahi, alo, wthi, wtlo, nullptr, qphi, qplo, 0.125f, 1, M, DD, DD);

    // ---- 2) kvp = kv @ Wkv, split epilogue ----
    split_act<<<nact / 4 / 256, tb>>>(kv, ahi, alo, nact);
    transpose_split<<<dim3((2 * DD) / 32, DD / 32), tt>>>(Wkv, wthi, wtlo, DD, 2 * DD);
    gemm_tc<<<dim3((2 * DD) / 256, M / 128), tb, GEMM_SMEM>>>(
        ahi, alo, wthi, wtlo, nullptr, kvphi, kvplo, 1.0f, 1, M, 2 * DD, DD);

    // ---- 3) tensor-core flash attention -> ao split (reuses ahi/alo) ----
    attn_tc<<<dim3(NN / 64, HH, BB), dim3(128), ATTN_SMEM>>>(qphi, qplo, kvphi, kvplo, ahi, alo);

    // ---- 4) out = ao @ Wout, fp32 epilogue ----
    transpose_split<<<dim3(DD / 32, DD / 32), tt>>>(Wout, wthi, wtlo, DD, DD);
    gemm_tc<<<dim3(DD / 256, M / 128), tb, GEMM_SMEM>>>(
        ahi, alo, wthi, wtlo, out, nullptr, nullptr, 1.0f, 0, M, DD, DD);
}

// round 9
// speedup vs baseline: 3.7884x; 1.1378x over previous
#include <cuda_runtime.h>
#include <cuda_bf16.h>
#include <cuda_fp16.h>
#include <cstdint>

// Problem constants (fixed shapes per reference)
#define BB   2
#define NN   2048
#define DD   1024
#define HH   16
#define DHH  64
#define NT   (NN / 64)   // 32 KV tiles of 64

// ---------------- scratch (__device__ globals; allocation is forbidden) ----------------
__device__ __align__(16) __nv_bfloat16 g_sqh [BB * NN * DD];     // split(q) hi
__device__ __align__(16) __nv_bfloat16 g_sql [BB * NN * DD];     // split(q) lo
__device__ __align__(16) __nv_bfloat16 g_skvh[BB * NN * DD];     // split(kv) hi
__device__ __align__(16) __nv_bfloat16 g_skvl[BB * NN * DD];     // split(kv) lo
__device__ __align__(16) __nv_bfloat16 g_qph [BB * NN * DD];     // qp hi (0.125 folded)
__device__ __align__(16) __nv_bfloat16 g_qpl [BB * NN * DD];     // qp lo
__device__ __align__(16) __nv_bfloat16 g_kh  [BB * NN * DD];     // K hi (bf16)
__device__ __align__(16) __nv_bfloat16 g_kl  [BB * NN * DD];     // K lo (bf16)
__device__ __align__(16) __half        g_vh  [BB * NN * DD];     // V (fp16, single)
__device__ __align__(16) __half        g_aoh [BB * NN * DD];     // ao hi (fp16)
__device__ __align__(16) __half        g_aol [BB * NN * DD];     // ao lo (fp16)
__device__ __align__(16) __nv_bfloat16 g_wtq_h [DD * DD];        // Wq^T hi
__device__ __align__(16) __nv_bfloat16 g_wtq_l [DD * DD];        // Wq^T lo
__device__ __align__(16) __nv_bfloat16 g_wtkv_h[2 * DD * DD];    // Wkv^T hi
__device__ __align__(16) __nv_bfloat16 g_wtkv_l[2 * DD * DD];    // Wkv^T lo
__device__ __align__(16) __half        g_wto_h [DD * DD];        // Wout^T (fp16, single)

// ---------------- helpers ----------------
__device__ __forceinline__ uint32_t smem_to_u32(const void* p) {
    uint32_t a;
    asm("{ .reg .u64 t; cvta.to.shared.u64 t, %1; cvt.u32.u64 %0, t; }" : "=r"(a) : "l"(p));
    return a;
}
#define SMEM_SWIZZLE_128B(off) ((off) ^ (((off) >> 3) & 0x70))

__device__ __forceinline__ void cp_async16(uint32_t s, const void* g) {
    asm volatile("cp.async.cg.shared.global [%0], [%1], 16;" :: "r"(s), "l"(g));
}
#define CP_COMMIT() asm volatile("cp.async.commit_group;" ::: "memory")
#define CP_WAIT0()  asm volatile("cp.async.wait_group 0;" ::: "memory")
#define CP_WAIT1()  asm volatile("cp.async.wait_group 1;" ::: "memory")

#define LDSM_X4(r0, r1, r2, r3, addr) \
    asm volatile("ldmatrix.sync.aligned.m8n8.x4.shared.b16 {%0,%1,%2,%3}, [%4];" \
                 : "=r"(r0), "=r"(r1), "=r"(r2), "=r"(r3) : "r"(addr))
#define LDSM_X4_T(r0, r1, r2, r3, addr) \
    asm volatile("ldmatrix.sync.aligned.m8n8.x4.trans.shared.b16 {%0,%1,%2,%3}, [%4];" \
                 : "=r"(r0), "=r"(r1), "=r"(r2), "=r"(r3) : "r"(addr))

template<bool HALF>
__device__ __forceinline__ void mma16816(float* d, const uint32_t* a, const uint32_t* b) {
    if (HALF) {
        asm volatile("mma.sync.aligned.m16n8k16.row.col.f32.f16.f16.f32 "
            "{%0,%1,%2,%3},{%4,%5,%6,%7},{%8,%9},{%0,%1,%2,%3};"
            : "+f"(d[0]), "+f"(d[1]), "+f"(d[2]), "+f"(d[3])
            : "r"(a[0]), "r"(a[1]), "r"(a[2]), "r"(a[3]), "r"(b[0]), "r"(b[1]));
    } else {
        asm volatile("mma.sync.aligned.m16n8k16.row.col.f32.bf16.bf16.f32 "
            "{%0,%1,%2,%3},{%4,%5,%6,%7},{%8,%9},{%0,%1,%2,%3};"
            : "+f"(d[0]), "+f"(d[1]), "+f"(d[2]), "+f"(d[3])
            : "r"(a[0]), "r"(a[1]), "r"(a[2]), "r"(a[3]), "r"(b[0]), "r"(b[1]));
    }
}

// bf16 pack helpers (bf16 bits == truncated fp32 top half)
__device__ __forceinline__ uint32_t pkbf(float lo, float hi) {
    uint32_t r; asm("cvt.rn.bf16x2.f32 %0, %1, %2;" : "=r"(r) : "f"(hi), "f"(lo)); return r;
}
__device__ __forceinline__ float lo2f(uint32_t u) { return __uint_as_float(u << 16); }
__device__ __forceinline__ float hi2f(uint32_t u) { return __uint_as_float(u & 0xffff0000u); }
// fp16 pack helper
__device__ __forceinline__ uint32_t h2u(__half2 h) { return *reinterpret_cast<uint32_t*>(&h); }

// =====================================================================================
// Prep: fused split of q and kv (grid.z selects); fused transpose of all 3 weights.
// =====================================================================================
__global__ __launch_bounds__(256)
void split_both(const float* __restrict__ q, const float* __restrict__ kv,
                __nv_bfloat16* __restrict__ qh, __nv_bfloat16* __restrict__ ql,
                __nv_bfloat16* __restrict__ kvh, __nv_bfloat16* __restrict__ kvl)
{
    const float* x = blockIdx.z ? kv : q;
    __nv_bfloat16* hi = blockIdx.z ? kvh : qh;
    __nv_bfloat16* lo = blockIdx.z ? kvl : ql;
    int i = (blockIdx.x * 256 + threadIdx.x) * 4;
    float4 v = *(const float4*)(x + i);
    uint32_t h01 = pkbf(v.x, v.y), h23 = pkbf(v.z, v.w);
    uint32_t l01 = pkbf(v.x - lo2f(h01), v.y - hi2f(h01));
    uint32_t l23 = pkbf(v.z - lo2f(h23), v.w - hi2f(h23));
    *(uint32_t*)(hi + i)     = h01;
    *(uint32_t*)(hi + i + 2) = h23;
    *(uint32_t*)(lo + i)     = l01;
    *(uint32_t*)(lo + i + 2) = l23;
}

// z=0: Wq[1024,1024]->bf16 pair; z=1: Wkv[1024,2048]->bf16 pair; z=2: Wout->fp16 single
__global__ __launch_bounds__(256)
void transpose_all(const float* __restrict__ Wq, const float* __restrict__ Wkv,
                   const float* __restrict__ Wout,
                   __nv_bfloat16* __restrict__ Tqh, __nv_bfloat16* __restrict__ Tql,
                   __nv_bfloat16* __restrict__ Tkvh, __nv_bfloat16* __restrict__ Tkvl,
                   __half* __restrict__ Toh)
{
    const int z = blockIdx.z;
    const int Nd = (z == 1) ? 2 * DD : DD;
    const int nb = blockIdx.x * 32, kb = blockIdx.y * 32;
    if (nb >= Nd) return;
    const float* W = (z == 0) ? Wq : (z == 1) ? Wkv : Wout;

    __shared__ float t[32][33];
    int tx = threadIdx.x & 31, ty = threadIdx.x >> 5;   // (32, 8)
    #pragma unroll
    for (int i = 0; i < 32; i += 8)
        t[ty + i][tx] = W[(size_t)(kb + ty + i) * Nd + nb + tx];
    __syncthreads();
    #pragma unroll
    for (int i = 0; i < 32; i += 8) {
        float v = t[tx][ty + i];                        // = W[kb+tx][nb+ty+i]
        size_t o = (size_t)(nb + ty + i) * DD + kb + tx;
        if (z == 2) {
            Toh[o] = __float2half(v);
        } else {
            __nv_bfloat16 h = __float2bfloat16(v);
            float r = v - __bfloat162float(h);
            if (z == 0) { Tqh[o] = h;  Tql[o] = __float2bfloat16(r); }
            else        { Tkvh[o] = h; Tkvl[o] = __float2bfloat16(r); }
        }
    }
}

// =====================================================================================
// mma.sync split GEMM, templated:
//  NPROD = 3: products ah*bh + ah*bl + al*bh  (B is a hi/lo pair)
//  NPROD = 2: products ah*bh + al*bh          (B hi only; no Blo staging/LDSM)
//  HALF:  fp16 operands+MMA (else bf16)
//  MODE:  0 = fp32 C out; 1 = bf16 pair out (scale folded); 2 = KV out
//         (global col < DD -> bf16 pair into O1h/O1l stride DD; else fp16 single
//          into O2 stride DD at col-DD)
// CTA tile 128x256, BK=64, 2-stage cp.async pipeline. 8 warps 2(m) x 4(n).
// =====================================================================================
template<int NPROD, bool HALF, int MODE>
__global__ __launch_bounds__(256)
void gemm_tc(const uint16_t* __restrict__ Ahi, const uint16_t* __restrict__ Alo,
             const uint16_t* __restrict__ Bhi, const uint16_t* __restrict__ Blo,
             float* __restrict__ C, uint16_t* __restrict__ O1h, uint16_t* __restrict__ O1l,
             uint16_t* __restrict__ O2, float scale, int M, int N, int K)
{
    constexpr uint32_t OFF_AL = 16384;
    constexpr uint32_t OFF_BH = 32768;
    constexpr uint32_t OFF_BL = 65536;
    constexpr uint32_t STAGE  = (NPROD == 3) ? 98304u : 65536u;

    extern __shared__ char smem[];
    const uint32_t smem_base = smem_to_u32(smem);
    const int tid = threadIdx.x;
    const int wid = tid >> 5;
    const int lid = tid & 31;
    const int m0 = blockIdx.y * 128;
    const int n0 = blockIdx.x * 256;
    const int warp_m = (wid & 1) * 64;
    const int warp_n = (wid >> 1) * 64;

    float d[4][8][4];
    #pragma unroll
    for (int mi = 0; mi < 4; mi++)
        #pragma unroll
        for (int ni = 0; ni < 8; ni++)
            #pragma unroll
            for (int j = 0; j < 4; j++) d[mi][ni][j] = 0.f;

    const int NCH = K >> 6;

    // ---- staging lambda-equivalent (macro-free explicit) ----
    // A tiles: 128 rows x 128B: 4 iters. B tiles: 256 rows x 128B: 8 iters.
    {
        const uint32_t sb = smem_base;
        #pragma unroll
        for (int it = 0; it < 4; it++) {
            int idx = tid + it * 256, row = idx >> 3, seg = idx & 7;
            uint32_t so = SMEM_SWIZZLE_128B((uint32_t)(row * 128 + seg * 16));
            cp_async16(sb + so,          Ahi + (size_t)(m0 + row) * K + seg * 8);
            cp_async16(sb + OFF_AL + so, Alo + (size_t)(m0 + row) * K + seg * 8);
        }
        #pragma unroll
        for (int it = 0; it < 8; it++) {
            int idx = tid + it * 256, row = idx >> 3, seg = idx & 7;
            uint32_t so = SMEM_SWIZZLE_128B((uint32_t)(row * 128 + seg * 16));
            cp_async16(sb + OFF_BH + so, Bhi + (size_t)(n0 + row) * K + seg * 8);
            if (NPROD == 3)
                cp_async16(sb + OFF_BL + so, Blo + (size_t)(n0 + row) * K + seg * 8);
        }
    }
    CP_COMMIT();
    CP_WAIT0();
    __syncthreads();

    for (int c = 0; c < NCH; c++) {
        const uint32_t sb = smem_base + (c & 1) * STAGE;

        if (c + 1 < NCH) {
            const uint32_t nb = smem_base + ((c + 1) & 1) * STAGE;
            const int kc = (c + 1) << 6;
            #pragma unroll
            for (int it = 0; it < 4; it++) {
                int idx = tid + it * 256, row = idx >> 3, seg = idx & 7;
                uint32_t so = SMEM_SWIZZLE_128B((uint32_t)(row * 128 + seg * 16));
                cp_async16(nb + so,          Ahi + (size_t)(m0 + row) * K + kc + seg * 8);
                cp_async16(nb + OFF_AL + so, Alo + (size_t)(m0 + row) * K + kc + seg * 8);
            }
            #pragma unroll
            for (int it = 0; it < 8; it++) {
                int idx = tid + it * 256, row = idx >> 3, seg = idx & 7;
                uint32_t so = SMEM_SWIZZLE_128B((uint32_t)(row * 128 + seg * 16));
                cp_async16(nb + OFF_BH + so, Bhi + (size_t)(n0 + row) * K + kc + seg * 8);
                if (NPROD == 3)
                    cp_async16(nb + OFF_BL + so, Blo + (size_t)(n0 + row) * K + kc + seg * 8);
            }
            CP_COMMIT();
        }

        #pragma unroll
        for (int ks = 0; ks < 4; ks++) {
            uint32_t ah[4][4], al[4][4];
            #pragma unroll
            for (int mi = 0; mi < 4; mi++) {
                uint32_t off = SMEM_SWIZZLE_128B(
                    (uint32_t)((warp_m + mi * 16 + (lid & 15)) * 128 + ks * 32 + ((lid >> 4) & 1) * 16));
                LDSM_X4(ah[mi][0], ah[mi][1], ah[mi][2], ah[mi][3], sb + off);
                LDSM_X4(al[mi][0], al[mi][1], al[mi][2], al[mi][3], sb + OFF_AL + off);
            }
            uint32_t bh[8][2], bl[8][2];
            #pragma unroll
            for (int pr = 0; pr < 4; pr++) {
                uint32_t off = SMEM_SWIZZLE_128B(
                    (uint32_t)((warp_n + pr * 16 + ((lid >> 4) & 1) * 8 + (lid & 7)) * 128
                               + ks * 32 + ((lid >> 3) & 1) * 16));
                LDSM_X4(bh[pr * 2][0], bh[pr * 2][1], bh[pr * 2 + 1][0], bh[pr * 2 + 1][1],
                        sb + OFF_BH + off);
                if (NPROD == 3)
                    LDSM_X4(bl[pr * 2][0], bl[pr * 2][1], bl[pr * 2 + 1][0], bl[pr * 2 + 1][1],
                            sb + OFF_BL + off);
            }
            #pragma unroll
            for (int mi = 0; mi < 4; mi++)
                #pragma unroll
                for (int ni = 0; ni < 8; ni++)
                    mma16816<HALF>(d[mi][ni], ah[mi], bh[ni]);
            if (NPROD == 3) {
                #pragma unroll
                for (int mi = 0; mi < 4; mi++)
                    #pragma unroll
                    for (int ni = 0; ni < 8; ni++)
                        mma16816<HALF>(d[mi][ni], ah[mi], bl[ni]);
            }
            #pragma unroll
            for (int mi = 0; mi < 4; mi++)
                #pragma unroll
                for (int ni = 0; ni < 8; ni++)
                    mma16816<HALF>(d[mi][ni], al[mi], bh[ni]);
        }

        if (c + 1 < NCH) {
            CP_WAIT0();
            __syncthreads();
        }
    }

    // ---- epilogue ----
    #pragma unroll
    for (int mi = 0; mi < 4; mi++) {
        const int row = m0 + warp_m + mi * 16 + (lid >> 2);
        #pragma unroll
        for (int ni = 0; ni < 8; ni++) {
            const int col = n0 + warp_n + ni * 8 + (lid & 3) * 2;
            float v0 = d[mi][ni][0], v1 = d[mi][ni][1];
            float v2 = d[mi][ni][2], v3 = d[mi][ni][3];
            if (MODE == 0) {
                *(float2*)(C + (size_t)row * N + col)       = make_float2(v0, v1);
                *(float2*)(C + (size_t)(row + 8) * N + col) = make_float2(v2, v3);
            } else if (MODE == 1) {
                v0 *= scale; v1 *= scale; v2 *= scale; v3 *= scale;
                uint32_t h01 = pkbf(v0, v1), h23 = pkbf(v2, v3);
                uint32_t l01 = pkbf(v0 - lo2f(h01), v1 - hi2f(h01));
                uint32_t l23 = pkbf(v2 - lo2f(h23), v3 - hi2f(h23));
                *(uint32_t*)(O1h + (size_t)row * N + col)       = h01;
                *(uint32_t*)(O1l + (size_t)row * N + col)       = l01;
                *(uint32_t*)(O1h + (size_t)(row + 8) * N + col) = h23;
                *(uint32_t*)(O1l + (size_t)(row + 8) * N + col) = l23;
            } else {   // MODE 2: KV split output
                if (col < DD) {   // K half -> bf16 pair, stride DD
                    uint32_t h01 = pkbf(v0, v1), h23 = pkbf(v2, v3);
                    uint32_t l01 = pkbf(v0 - lo2f(h01), v1 - hi2f(h01));
                    uint32_t l23 = pkbf(v2 - lo2f(h23), v3 - hi2f(h23));
                    *(uint32_t*)(O1h + (size_t)row * DD + col)       = h01;
                    *(uint32_t*)(O1l + (size_t)row * DD + col)       = l01;
                    *(uint32_t*)(O1h + (size_t)(row + 8) * DD + col) = h23;
                    *(uint32_t*)(O1l + (size_t)(row + 8) * DD + col) = l23;
                } else {          // V half -> fp16 single, stride DD
                    const int cv = col - DD;
                    __half2 a = __floats2half2_rn(v0, v1);
                    __half2 b = __floats2half2_rn(v2, v3);
                    *(uint32_t*)(O2 + (size_t)row * DD + cv)       = h2u(a);
                    *(uint32_t*)(O2 + (size_t)(row + 8) * DD + cv) = h2u(b);
                }
            }
        }
    }
}

// =====================================================================================
// Tensor-core flash attention v3: 128-thread CTAs (4 warps, 64 Q rows), 3 CTAs/SM.
// QK^T: bf16 3-product (softmax-amplified -> keep precise).
// PV:   fp16 2-product (P split into fp16 pair; V fp16 hi-only).
// Stage: Khi 8KB | Klo 8KB | Vh 8KB = 24KB, double buffered (48KB).
// ao written as fp16 pair for the 2-product output projection.
// =====================================================================================
#define AT_STAGE 24576
#define ATTN_SMEM (2 * AT_STAGE)

__device__ __forceinline__ void stage_kv(int tid, uint32_t buf,
                                         const __nv_bfloat16* kh, const __nv_bfloat16* kl,
                                         const __half* vh, int t)
{
    #pragma unroll
    for (int it = 0; it < 4; it++) {
        int idx = tid + it * 128, row = idx >> 3, seg = idx & 7;
        uint32_t so = SMEM_SWIZZLE_128B((uint32_t)(row * 128 + seg * 16));
        cp_async16(buf + so,         kh + (size_t)(t * 64 + row) * DD + seg * 8);
        cp_async16(buf + 8192 + so,  kl + (size_t)(t * 64 + row) * DD + seg * 8);
        cp_async16(buf + 16384 + so, vh + (size_t)(t * 64 + row) * DD + seg * 8);
    }
}

__global__ __launch_bounds__(128)
void attn_tc(const __nv_bfloat16* __restrict__ qph, const __nv_bfloat16* __restrict__ qpl,
             const __nv_bfloat16* __restrict__ gkh, const __nv_bfloat16* __restrict__ gkl,
             const __half* __restrict__ gvh,
             __half* __restrict__ aoh, __half* __restrict__ aol)
{
    extern __shared__ char smem[];
    const uint32_t smb = smem_to_u32(smem);
    const int tid = threadIdx.x;
    const int wid = tid >> 5;          // 0..3
    const int lid = tid & 31;
    const int b = blockIdx.z, h = blockIdx.y;
    const int q0 = blockIdx.x * 64;
    const int gr = lid >> 2, ci = lid & 3;

    // ---- Q fragments (bf16 pair, loop-invariant; 0.125 folded) ----
    const size_t qr0 = ((size_t)(b * NN + q0 + wid * 16 + gr)) * DD + h * DHH;
    const size_t qr1 = qr0 + 8 * DD;
    uint32_t qh[4][4], ql[4][4];
    #pragma unroll
    for (int ks = 0; ks < 4; ks++) {
        const int k0 = ks * 16 + ci * 2;
        qh[ks][0] = *(const uint32_t*)(qph + qr0 + k0);
        qh[ks][1] = *(const uint32_t*)(qph + qr1 + k0);
        qh[ks][2] = *(const uint32_t*)(qph + qr0 + k0 + 8);
        qh[ks][3] = *(const uint32_t*)(qph + qr1 + k0 + 8);
        ql[ks][0] = *(const uint32_t*)(qpl + qr0 + k0);
        ql[ks][1] = *(const uint32_t*)(qpl + qr1 + k0);
        ql[ks][2] = *(const uint32_t*)(qpl + qr0 + k0 + 8);
        ql[ks][3] = *(const uint32_t*)(qpl + qr1 + k0 + 8);
    }

    const __nv_bfloat16* kh = gkh + (size_t)(b * NN) * DD + h * DHH;
    const __nv_bfloat16* kl = gkl + (size_t)(b * NN) * DD + h * DHH;
    const __half*        vh = gvh + (size_t)(b * NN) * DD + h * DHH;

    float oacc[8][4];
    #pragma unroll
    for (int nf = 0; nf < 8; nf++)
        #pragma unroll
        for (int j = 0; j < 4; j++) oacc[nf][j] = 0.f;
    float m0 = -1e30f, m1 = -1e30f, l0 = 0.f, l1 = 0.f;

    stage_kv(tid, smb, kh, kl, vh, 0);
    CP_COMMIT();

    for (int t = 0; t < NT; t++) {
        if (t + 1 < NT) {
            stage_kv(tid, smb + ((t + 1) & 1) * AT_STAGE, kh, kl, vh, t + 1);
            CP_COMMIT();
            CP_WAIT1();
        } else {
            CP_WAIT0();
        }
        __syncthreads();
        const uint32_t kb = smb + (t & 1) * AT_STAGE;

        // ---- S = Q K^T : bf16 3-product ----
        float sacc[8][4];
        #pragma unroll
        for (int nf = 0; nf < 8; nf++)
            #pragma unroll
            for (int j = 0; j < 4; j++) sacc[nf][j] = 0.f;

        #pragma unroll
        for (int ks = 0; ks < 4; ks++) {
            uint32_t bh[8][2], bl[8][2];
            #pragma unroll
            for (int pr = 0; pr < 4; pr++) {
                uint32_t off = SMEM_SWIZZLE_128B(
                    (uint32_t)((pr * 16 + ((lid >> 4) & 1) * 8 + (lid & 7)) * 128
                               + ks * 32 + ((lid >> 3) & 1) * 16));
                LDSM_X4(bh[pr * 2][0], bh[pr * 2][1], bh[pr * 2 + 1][0], bh[pr * 2 + 1][1],
                        kb + off);
                LDSM_X4(bl[pr * 2][0], bl[pr * 2][1], bl[pr * 2 + 1][0], bl[pr * 2 + 1][1],
                        kb + 8192 + off);
            }
            #pragma unroll
            for (int nf = 0; nf < 8; nf++) mma16816<false>(sacc[nf], qh[ks], bh[nf]);
            #pragma unroll
            for (int nf = 0; nf < 8; nf++) mma16816<false>(sacc[nf], qh[ks], bl[nf]);
            #pragma unroll
            for (int nf = 0; nf < 8; nf++) mma16816<false>(sacc[nf], ql[ks], bh[nf]);
        }

        // ---- online softmax (rows gr, gr+8; quad lanes share a row) ----
        float mt0 = -1e30f, mt1 = -1e30f;
        #pragma unroll
        for (int nf = 0; nf < 8; nf++) {
            mt0 = fmaxf(mt0, fmaxf(sacc[nf][0], sacc[nf][1]));
            mt1 = fmaxf(mt1, fmaxf(sacc[nf][2], sacc[nf][3]));
        }
        mt0 = fmaxf(mt0, __shfl_xor_sync(0xffffffffu, mt0, 1));
        mt0 = fmaxf(mt0, __shfl_xor_sync(0xffffffffu, mt0, 2));
        mt1 = fmaxf(mt1, __shfl_xor_sync(0xffffffffu, mt1, 1));
        mt1 = fmaxf(mt1, __shfl_xor_sync(0xffffffffu, mt1, 2));
        const float mn0 = fmaxf(m0, mt0), mn1 = fmaxf(m1, mt1);
        const float al0 = __expf(m0 - mn0), al1 = __expf(m1 - mn1);
        m0 = mn0; m1 = mn1;
        float rs0 = 0.f, rs1 = 0.f;
        #pragma unroll
        for (int nf = 0; nf < 8; nf++) {
            sacc[nf][0] = __expf(sacc[nf][0] - mn0);
            sacc[nf][1] = __expf(sacc[nf][1] - mn0);
            sacc[nf][2] = __expf(sacc[nf][2] - mn1);
            sacc[nf][3] = __expf(sacc[nf][3] - mn1);
            rs0 += sacc[nf][0] + sacc[nf][1];
            rs1 += sacc[nf][2] + sacc[nf][3];
        }
        rs0 += __shfl_xor_sync(0xffffffffu, rs0, 1);
        rs0 += __shfl_xor_sync(0xffffffffu, rs0, 2);
        rs1 += __shfl_xor_sync(0xffffffffu, rs1, 1);
        rs1 += __shfl_xor_sync(0xffffffffu, rs1, 2);
        l0 = l0 * al0 + rs0;
        l1 = l1 * al1 + rs1;
        #pragma unroll
        for (int nf = 0; nf < 8; nf++) {
            oacc[nf][0] *= al0; oacc[nf][1] *= al0;
            oacc[nf][2] *= al1; oacc[nf][3] *= al1;
        }

        // ---- O += P V : fp16 2-product (P split into fp16 pair; V hi-only) ----
        #pragma unroll
        for (int ks = 0; ks < 4; ks++) {
            uint32_t aPh[4], aPl[4];
            {
                const float c0 = sacc[2 * ks][0],     c1 = sacc[2 * ks][1];
                const float c2 = sacc[2 * ks][2],     c3 = sacc[2 * ks][3];
                const float e0 = sacc[2 * ks + 1][0], e1 = sacc[2 * ks + 1][1];
                const float e2 = sacc[2 * ks + 1][2], e3 = sacc[2 * ks + 1][3];
                __half2 h0 = __floats2half2_rn(c0, c1), h1 = __floats2half2_rn(c2, c3);
                __half2 h2 = __floats2half2_rn(e0, e1), h3 = __floats2half2_rn(e2, e3);
                float2 f0 = __half22float2(h0), f1 = __half22float2(h1);
                float2 f2 = __half22float2(h2), f3 = __half22float2(h3);
                __half2 p0 = __floats2half2_rn(c0 - f0.x, c1 - f0.y);
                __half2 p1 = __floats2half2_rn(c2 - f1.x, c3 - f1.y);
                __half2 p2 = __floats2half2_rn(e0 - f2.x, e1 - f2.y);
                __half2 p3 = __floats2half2_rn(e2 - f3.x, e3 - f3.y);
                aPh[0] = h2u(h0); aPh[1] = h2u(h1); aPh[2] = h2u(h2); aPh[3] = h2u(h3);
                aPl[0] = h2u(p0); aPl[1] = h2u(p1); aPl[2] = h2u(p2); aPl[3] = h2u(p3);
            }
            uint32_t vf[8][2];
            #pragma unroll
            for (int nfp = 0; nfp < 4; nfp++) {
                uint32_t off = SMEM_SWIZZLE_128B(
                    (uint32_t)((ks * 16 + ((lid >> 3) & 1) * 8 + (lid & 7)) * 128
                               + (2 * nfp + ((lid >> 4) & 1)) * 16));
                LDSM_X4_T(vf[2 * nfp][0], vf[2 * nfp][1], vf[2 * nfp + 1][0], vf[2 * nfp + 1][1],
                          kb + 16384 + off);
            }
            #pragma unroll
            for (int nf = 0; nf < 8; nf++) mma16816<true>(oacc[nf], aPh, vf[nf]);
            #pragma unroll
            for (int nf = 0; nf < 8; nf++) mma16816<true>(oacc[nf], aPl, vf[nf]);
        }
        __syncthreads();
    }

    // ---- epilogue: normalize, split to fp16 pair, write head-merged ao ----
    const float inv0 = 1.0f / l0, inv1 = 1.0f / l1;
    const size_t or0 = ((size_t)(b * NN + q0 + wid * 16 + gr)) * DD + h * DHH;
    const size_t or1 = or0 + 8 * DD;
    #pragma unroll
    for (int nf = 0; nf < 8; nf++) {
        const int col = nf * 8 + ci * 2;
        float v0 = oacc[nf][0] * inv0, v1 = oacc[nf][1] * inv0;
        float v2 = oacc[nf][2] * inv1, v3 = oacc[nf][3] * inv1;
        __half2 h01 = __floats2half2_rn(v0, v1), h23 = __floats2half2_rn(v2, v3);
        float2 f01 = __half22float2(h01), f23 = __half22float2(h23);
        __half2 l01 = __floats2half2_rn(v0 - f01.x, v1 - f01.y);
        __half2 l23 = __floats2half2_rn(v2 - f23.x, v3 - f23.y);
        *(uint32_t*)(aoh + or0 + col) = h2u(h01);
        *(uint32_t*)(aol + or0 + col) = h2u(l01);
        *(uint32_t*)(aoh + or1 + col) = h2u(h23);
        *(uint32_t*)(aol + or1 + col) = h2u(l23);
    }
}

// =====================================================================================
// Launch
// =====================================================================================
extern "C" void kernel_launch(void* const* d_in, const int* in_sizes, int n_in,
                              void* d_out, int out_size)
{
    const float* q    = (const float*)d_in[0];
    const float* kv   = (const float*)d_in[1];
    const float* Wq   = (const float*)d_in[2];
    const float* Wkv  = (const float*)d_in[3];
    const float* Wout = (const float*)d_in[4];
    float* out = (float*)d_out;

    __nv_bfloat16 *sqh, *sql, *skvh, *skvl, *qph, *qpl, *kh, *kl;
    __nv_bfloat16 *wtq_h, *wtq_l, *wtkv_h, *wtkv_l;
    __half *vh, *aoh, *aol, *wto_h;
    cudaGetSymbolAddress((void**)&sqh,    g_sqh);
    cudaGetSymbolAddress((void**)&sql,    g_sql);
    cudaGetSymbolAddress((void**)&skvh,   g_skvh);
    cudaGetSymbolAddress((void**)&skvl,   g_skvl);
    cudaGetSymbolAddress((void**)&qph,    g_qph);
    cudaGetSymbolAddress((void**)&qpl,    g_qpl);
    cudaGetSymbolAddress((void**)&kh,     g_kh);
    cudaGetSymbolAddress((void**)&kl,     g_kl);
    cudaGetSymbolAddress((void**)&vh,     g_vh);
    cudaGetSymbolAddress((void**)&aoh,    g_aoh);
    cudaGetSymbolAddress((void**)&aol,    g_aol);
    cudaGetSymbolAddress((void**)&wtq_h,  g_wtq_h);
    cudaGetSymbolAddress((void**)&wtq_l,  g_wtq_l);
    cudaGetSymbolAddress((void**)&wtkv_h, g_wtkv_h);
    cudaGetSymbolAddress((void**)&wtkv_l, g_wtkv_l);
    cudaGetSymbolAddress((void**)&wto_h,  g_wto_h);

    const int M = BB * NN;              // 4096
    const int nact = M * DD;            // 4M elements per input

    cudaFuncSetAttribute(gemm_tc<3, false, 1>, cudaFuncAttributeMaxDynamicSharedMemorySize, 196608);
    cudaFuncSetAttribute(gemm_tc<3, false, 2>, cudaFuncAttributeMaxDynamicSharedMemorySize, 196608);
    cudaFuncSetAttribute(gemm_tc<2, true, 0>,  cudaFuncAttributeMaxDynamicSharedMemorySize, 131072);
    cudaFuncSetAttribute(attn_tc, cudaFuncAttributeMaxDynamicSharedMemorySize, ATTN_SMEM);

    dim3 tb(256);

    // ---- prep: fused splits + fused weight transposes ----
    split_both<<<dim3(nact / 4 / 256, 1, 2), tb>>>(q, kv, sqh, sql, skvh, skvl);
    transpose_all<<<dim3(64, 32, 3), tb>>>(Wq, Wkv, Wout, wtq_h, wtq_l, wtkv_h, wtkv_l, wto_h);

    // ---- 1) qp = (q @ Wq) * 0.125 -> bf16 pair ----
    gemm_tc<3, false, 1><<<dim3(DD / 256, M / 128), tb, 196608>>>(
        (const uint16_t*)sqh, (const uint16_t*)sql,
        (const uint16_t*)wtq_h, (const uint16_t*)wtq_l,
        nullptr, (uint16_t*)qph, (uint16_t*)qpl, nullptr, 0.125f, M, DD, DD);

    // ---- 2) kvp = kv @ Wkv -> K bf16 pair + V fp16 single ----
    gemm_tc<3, false, 2><<<dim3((2 * DD) / 256, M / 128), tb, 196608>>>(
        (const uint16_t*)skvh, (const uint16_t*)skvl,
        (const uint16_t*)wtkv_h, (const uint16_t*)wtkv_l,
        nullptr, (uint16_t*)kh, (uint16_t*)kl, (uint16_t*)vh, 1.0f, M, 2 * DD, DD);

    // ---- 3) tensor-core flash attention -> ao fp16 pair ----
    attn_tc<<<dim3(NN / 64, HH, BB), dim3(128), ATTN_SMEM>>>(qph, qpl, kh, kl, vh, aoh, aol);

    // ---- 4) out = ao @ Wout (fp16 2-product, fp32 out) ----
    gemm_tc<2, true, 0><<<dim3(DD / 256, M / 128), tb, 131072>>>(
        (const uint16_t*)aoh, (const uint16_t*)aol,
        (const uint16_t*)wto_h, nullptr,
        out, nullptr, nullptr, nullptr, 1.0f, M, DD, DD);
}